// round 7
// baseline (speedup 1.0000x reference)
#include <cuda_runtime.h>
#include <cuda_bf16.h>
#include <math.h>
#include <stdint.h>

// ---------------- problem constants ----------------
#define BB 2
#define TT 1024
#define CC 256
#define FF 1024
#define EE 32
#define VV 50257
#define HH 8
#define DD 32
#define NN 2048   // B*T

#define NEGF (-3.3895313892515355e38f)   // -finfo(bf16).max

// ---------------- scratch (__device__ globals; no allocations allowed) ------
__device__ float g_hs [NN * CC];
__device__ float g_x  [NN * CC];
__device__ float g_q  [NN * CC];
__device__ float g_k  [NN * CC];
__device__ float g_v  [NN * CC];
__device__ float g_ao [NN * CC];
__device__ float g_xt [NN * CC];
__device__ float g_hsf[NN * CC];
__device__ float g_lraw[NN * EE];
__device__ float g_rw  [NN * EE];
__device__ float g_xnorm[NN];
__device__ float g_snorm[EE];
__device__ int   g_cnt [EE];
__device__ int   g_list[EE * NN];
__device__ float g_h[(size_t)EE * NN * FF];   // expert hidden acts (compact rows)

// ---------------- embedding gather ----------------
__global__ void embed_k(const int* __restrict__ ids, const float* __restrict__ emb,
                        float* __restrict__ hs)
{
    int row = blockIdx.x, tid = threadIdx.x;
    hs[row * CC + tid] = emb[(long long)ids[row] * CC + tid];
}

// ---------------- layernorm (block per row, 256 threads = C) ----------------
__global__ void ln_k(const float* __restrict__ x, const float* __restrict__ w,
                     const float* __restrict__ b, float* __restrict__ y,
                     float* __restrict__ norms)
{
    int row = blockIdx.x, tid = threadIdx.x;
    __shared__ float red[CC];
    float v = x[row * CC + tid];

    red[tid] = v; __syncthreads();
    for (int s = CC / 2; s > 0; s >>= 1) {
        if (tid < s) red[tid] += red[tid + s];
        __syncthreads();
    }
    float mu = red[0] / CC;
    __syncthreads();

    float d = v - mu;
    red[tid] = d * d; __syncthreads();
    for (int s = CC / 2; s > 0; s >>= 1) {
        if (tid < s) red[tid] += red[tid + s];
        __syncthreads();
    }
    float var = red[0] / CC;
    __syncthreads();

    float ys = d * rsqrtf(var + 1e-5f) * w[tid] + b[tid];
    y[row * CC + tid] = ys;

    if (norms) {
        red[tid] = ys * ys; __syncthreads();
        for (int s = CC / 2; s > 0; s >>= 1) {
            if (tid < s) red[tid] += red[tid + s];
            __syncthreads();
        }
        if (tid == 0) norms[row] = sqrtf(red[0]);
    }
}

// ---------------- sim_matrix column norms ----------------
__global__ void snorm_k(const float* __restrict__ sim, float* __restrict__ sn)
{
    int e = blockIdx.x, tid = threadIdx.x;
    __shared__ float red[CC];
    float v = sim[(long long)tid * EE + e];
    red[tid] = v * v; __syncthreads();
    for (int s = CC / 2; s > 0; s >>= 1) {
        if (tid < s) red[tid] += red[tid + s];
        __syncthreads();
    }
    if (tid == 0) sn[e] = fmaxf(sqrtf(red[0]), 1e-12f);
}

// ---------------- generic fp32 SGEMM, 128x128x8 tile, 8x8/thread ------------
// (kept for precision-critical small GEMMs: QKV, attn-out, gate logits)
template <int FLAGS, bool ALIGNED_B>
__global__ __launch_bounds__(256, 2)
void sgemm_k(const float* __restrict__ A, const float* __restrict__ B,
             float* __restrict__ Cout, const float* __restrict__ Src,
             int M, int Nn, int K, int lda, int ldb, int ldc)
{
    __shared__ float As[2][8][128];
    __shared__ float Bs[2][8][132];

    const int tid = threadIdx.x;
    const int tx = tid & 15, ty = tid >> 4;
    const int m0 = blockIdx.y * 128, n0 = blockIdx.x * 128;

    const int arow = tid >> 1, ak = (tid & 1) * 4;
    const int bk = tid >> 5, bn = (tid & 31) * 4;
    const bool aOK = (m0 + arow < M);
    const int nb0 = n0 + bn;
    const bool bVec = (nb0 + 3 < Nn);

    float acc[8][8];
    #pragma unroll
    for (int i = 0; i < 8; i++)
        #pragma unroll
        for (int j = 0; j < 8; j++) acc[i][j] = 0.f;

    float4 av;
    float  bv0, bv1, bv2, bv3;

    {
        av = make_float4(0.f, 0.f, 0.f, 0.f);
        if (aOK) av = *(const float4*)(A + (long long)(m0 + arow) * lda + ak);
        const long long brow = (long long)bk * ldb;
        if (ALIGNED_B && bVec) {
            float4 b4 = *(const float4*)(B + brow + nb0);
            bv0 = b4.x; bv1 = b4.y; bv2 = b4.z; bv3 = b4.w;
        } else {
            bv0 = (nb0 + 0 < Nn) ? B[brow + nb0 + 0] : 0.f;
            bv1 = (nb0 + 1 < Nn) ? B[brow + nb0 + 1] : 0.f;
            bv2 = (nb0 + 2 < Nn) ? B[brow + nb0 + 2] : 0.f;
            bv3 = (nb0 + 3 < Nn) ? B[brow + nb0 + 3] : 0.f;
        }
    }
    As[0][ak + 0][arow] = av.x;
    As[0][ak + 1][arow] = av.y;
    As[0][ak + 2][arow] = av.z;
    As[0][ak + 3][arow] = av.w;
    Bs[0][bk][bn + 0] = bv0;
    Bs[0][bk][bn + 1] = bv1;
    Bs[0][bk][bn + 2] = bv2;
    Bs[0][bk][bn + 3] = bv3;
    __syncthreads();

    int buf = 0;
    for (int k0 = 0; k0 < K; k0 += 8) {
        const bool hasNext = (k0 + 8 < K);
        if (hasNext) {
            av = make_float4(0.f, 0.f, 0.f, 0.f);
            if (aOK) av = *(const float4*)(A + (long long)(m0 + arow) * lda + (k0 + 8) + ak);
            const long long brow = (long long)(k0 + 8 + bk) * ldb;
            if (ALIGNED_B && bVec) {
                float4 b4 = *(const float4*)(B + brow + nb0);
                bv0 = b4.x; bv1 = b4.y; bv2 = b4.z; bv3 = b4.w;
            } else {
                bv0 = (nb0 + 0 < Nn) ? B[brow + nb0 + 0] : 0.f;
                bv1 = (nb0 + 1 < Nn) ? B[brow + nb0 + 1] : 0.f;
                bv2 = (nb0 + 2 < Nn) ? B[brow + nb0 + 2] : 0.f;
                bv3 = (nb0 + 3 < Nn) ? B[brow + nb0 + 3] : 0.f;
            }
        }

        #pragma unroll
        for (int kk = 0; kk < 8; kk++) {
            float a[8], bfr[8];
            #pragma unroll
            for (int i = 0; i < 8; i++) a[i] = As[buf][kk][ty * 8 + i];
            #pragma unroll
            for (int j = 0; j < 8; j++) bfr[j] = Bs[buf][kk][tx * 8 + j];
            #pragma unroll
            for (int i = 0; i < 8; i++)
                #pragma unroll
                for (int j = 0; j < 8; j++)
                    acc[i][j] = fmaf(a[i], bfr[j], acc[i][j]);
        }

        if (hasNext) {
            const int nb = buf ^ 1;
            As[nb][ak + 0][arow] = av.x;
            As[nb][ak + 1][arow] = av.y;
            As[nb][ak + 2][arow] = av.z;
            As[nb][ak + 3][arow] = av.w;
            Bs[nb][bk][bn + 0] = bv0;
            Bs[nb][bk][bn + 1] = bv1;
            Bs[nb][bk][bn + 2] = bv2;
            Bs[nb][bk][bn + 3] = bv3;
            __syncthreads();
            buf = nb;
        }
    }

    const int r0 = m0 + ty * 8, c0 = n0 + tx * 8;
    #pragma unroll
    for (int i = 0; i < 8; i++) {
        int r = r0 + i;
        if (r >= M) continue;
        #pragma unroll
        for (int j = 0; j < 8; j++) {
            int c = c0 + j;
            if (c >= Nn) continue;
            float v = acc[i][j];
            if (FLAGS & 2) v += Src[(long long)r * ldc + c];
            Cout[(long long)r * ldc + c] = v;
        }
    }
}

// ---------------- 3xTF32 mma building blocks --------------------------------
// Emulated fp32: hi = tf32(x), lo = tf32(x - hi); D += Ahi*Bhi + Ahi*Blo + Alo*Bhi.
// Block 128x128, 8 warps (2 m x 4 n), warp tile 64x32, m16n8k8 atoms.
__device__ __forceinline__ void tf32_split(float x, uint32_t& hi, uint32_t& lo)
{
    asm("cvt.rna.tf32.f32 %0, %1;" : "=r"(hi) : "f"(x));
    float r = x - __uint_as_float(hi);     // exact: hi has 11-bit mantissa
    asm("cvt.rna.tf32.f32 %0, %1;" : "=r"(lo) : "f"(r));
}

#define MMA_TF32(D, A0, A1, A2, A3, B0, B1)                                     \
    asm volatile("mma.sync.aligned.m16n8k8.row.col.f32.tf32.tf32.f32 "          \
                 "{%0,%1,%2,%3}, {%4,%5,%6,%7}, {%8,%9}, {%0,%1,%2,%3};"        \
                 : "+f"((D)[0]), "+f"((D)[1]), "+f"((D)[2]), "+f"((D)[3])       \
                 : "r"(A0), "r"(A1), "r"(A2), "r"(A3), "r"(B0), "r"(B1))

// One 8-deep K-step of the 64x32 warp tile (audited fragment mapping).
__device__ __forceinline__ void mma_step_3xtf32(
    const float As[8][132], const float Bs[8][132],
    float d[4][4][4], int wm0, int wn0, int gid, int tg)
{
    uint32_t ahi[4][4], alo[4][4];
    #pragma unroll
    for (int i = 0; i < 4; i++) {
        const int r = wm0 + i * 16 + gid;
        tf32_split(As[tg    ][r],     ahi[i][0], alo[i][0]);
        tf32_split(As[tg    ][r + 8], ahi[i][1], alo[i][1]);
        tf32_split(As[tg + 4][r],     ahi[i][2], alo[i][2]);
        tf32_split(As[tg + 4][r + 8], ahi[i][3], alo[i][3]);
    }
    #pragma unroll
    for (int j = 0; j < 4; j++) {
        const int c = wn0 + j * 8 + gid;
        uint32_t bh0, bl0, bh1, bl1;
        tf32_split(Bs[tg    ][c], bh0, bl0);
        tf32_split(Bs[tg + 4][c], bh1, bl1);
        #pragma unroll
        for (int i = 0; i < 4; i++) {
            MMA_TF32(d[i][j], ahi[i][0], ahi[i][1], ahi[i][2], ahi[i][3], bh0, bh1);
            MMA_TF32(d[i][j], ahi[i][0], ahi[i][1], ahi[i][2], ahi[i][3], bl0, bl1);
            MMA_TF32(d[i][j], alo[i][0], alo[i][1], alo[i][2], alo[i][3], bh0, bh1);
        }
    }
}

// ---------------- LM head: 3xTF32 tensor-core GEMM --------------------------
__global__ __launch_bounds__(256)
void lmhead_tf32_k(const float* __restrict__ A, const float* __restrict__ B,
                   float* __restrict__ Cout, int M, int Nn, int K, int ldb)
{
    __shared__ float As[2][8][132];
    __shared__ float Bs[2][8][132];

    const int tid = threadIdx.x;
    const int wid = tid >> 5, lane = tid & 31;
    const int wm0 = (wid >> 2) * 64;
    const int wn0 = (wid & 3) * 32;
    const int gid = lane >> 2, tg = lane & 3;
    const int m0 = blockIdx.y * 128, n0 = blockIdx.x * 128;

    const int arow = tid >> 1, ak = (tid & 1) * 4;
    const int bk = tid >> 5, bn = (tid & 31) * 4;
    const int nb0 = n0 + bn;

    float d[4][4][4];
    #pragma unroll
    for (int i = 0; i < 4; i++)
        #pragma unroll
        for (int j = 0; j < 4; j++)
            #pragma unroll
            for (int r = 0; r < 4; r++) d[i][j][r] = 0.f;

    float4 av;
    float bv0, bv1, bv2, bv3;

    av = *(const float4*)(A + (long long)(m0 + arow) * K + ak);
    {
        const long long brow = (long long)bk * ldb;
        bv0 = (nb0 + 0 < Nn) ? B[brow + nb0 + 0] : 0.f;
        bv1 = (nb0 + 1 < Nn) ? B[brow + nb0 + 1] : 0.f;
        bv2 = (nb0 + 2 < Nn) ? B[brow + nb0 + 2] : 0.f;
        bv3 = (nb0 + 3 < Nn) ? B[brow + nb0 + 3] : 0.f;
    }
    As[0][ak + 0][arow] = av.x; As[0][ak + 1][arow] = av.y;
    As[0][ak + 2][arow] = av.z; As[0][ak + 3][arow] = av.w;
    Bs[0][bk][bn + 0] = bv0; Bs[0][bk][bn + 1] = bv1;
    Bs[0][bk][bn + 2] = bv2; Bs[0][bk][bn + 3] = bv3;
    __syncthreads();

    int buf = 0;
    for (int k0 = 0; k0 < K; k0 += 8) {
        const bool hasNext = (k0 + 8 < K);
        if (hasNext) {
            av = *(const float4*)(A + (long long)(m0 + arow) * K + (k0 + 8) + ak);
            const long long brow = (long long)(k0 + 8 + bk) * ldb;
            bv0 = (nb0 + 0 < Nn) ? B[brow + nb0 + 0] : 0.f;
            bv1 = (nb0 + 1 < Nn) ? B[brow + nb0 + 1] : 0.f;
            bv2 = (nb0 + 2 < Nn) ? B[brow + nb0 + 2] : 0.f;
            bv3 = (nb0 + 3 < Nn) ? B[brow + nb0 + 3] : 0.f;
        }

        mma_step_3xtf32(As[buf], Bs[buf], d, wm0, wn0, gid, tg);

        if (hasNext) {
            const int nb = buf ^ 1;
            As[nb][ak + 0][arow] = av.x; As[nb][ak + 1][arow] = av.y;
            As[nb][ak + 2][arow] = av.z; As[nb][ak + 3][arow] = av.w;
            Bs[nb][bk][bn + 0] = bv0; Bs[nb][bk][bn + 1] = bv1;
            Bs[nb][bk][bn + 2] = bv2; Bs[nb][bk][bn + 3] = bv3;
            __syncthreads();
            buf = nb;
        }
    }

    #pragma unroll
    for (int i = 0; i < 4; i++) {
        const int row = m0 + wm0 + i * 16 + gid;
        #pragma unroll
        for (int j = 0; j < 4; j++) {
            const int col = n0 + wn0 + j * 8 + 2 * tg;
            if (col < Nn) {
                Cout[(long long)row * ldb + col] = d[i][j][0];
                Cout[(long long)(row + 8) * ldb + col] = d[i][j][2];
            }
            if (col + 1 < Nn) {
                Cout[(long long)row * ldb + col + 1] = d[i][j][1];
                Cout[(long long)(row + 8) * ldb + col + 1] = d[i][j][3];
            }
        }
    }
}

// ---------------- MoE up-proj: 3xTF32, gathered rows, gelu epilogue ---------
// grid: x = FF/128 (8), y = NN/128 (16), z = expert.
__global__ __launch_bounds__(256)
void moe_up_tf32_k(const float* __restrict__ xt, const float* __restrict__ w1,
                   float* __restrict__ hbuf)
{
    const int e = blockIdx.z;
    const int cnt = g_cnt[e];
    const int m0 = blockIdx.y * 128;
    if (m0 >= cnt) return;
    const int n0 = blockIdx.x * 128;

    const float* B = w1 + (long long)e * CC * FF;
    float* Cout = hbuf + (long long)e * NN * FF;

    __shared__ float As[2][8][132];
    __shared__ float Bs[2][8][132];
    __shared__ int toks[128];

    const int tid = threadIdx.x;
    if (tid < 128) toks[tid] = (m0 + tid < cnt) ? g_list[e * NN + m0 + tid] : -1;
    __syncthreads();

    const int wid = tid >> 5, lane = tid & 31;
    const int wm0 = (wid >> 2) * 64;
    const int wn0 = (wid & 3) * 32;
    const int gid = lane >> 2, tg = lane & 3;

    const int arow = tid >> 1, ak = (tid & 1) * 4;
    const int bk = tid >> 5, bn = (tid & 31) * 4;
    const int tokA = toks[arow];

    float d[4][4][4];
    #pragma unroll
    for (int i = 0; i < 4; i++)
        #pragma unroll
        for (int j = 0; j < 4; j++)
            #pragma unroll
            for (int r = 0; r < 4; r++) d[i][j][r] = 0.f;

    float4 av, bv;
    av = make_float4(0.f, 0.f, 0.f, 0.f);
    if (tokA >= 0) av = *(const float4*)(xt + (long long)tokA * CC + ak);
    bv = *(const float4*)(B + (long long)bk * FF + n0 + bn);
    As[0][ak + 0][arow] = av.x; As[0][ak + 1][arow] = av.y;
    As[0][ak + 2][arow] = av.z; As[0][ak + 3][arow] = av.w;
    *(float4*)&Bs[0][bk][bn] = bv;
    __syncthreads();

    int buf = 0;
    for (int k0 = 0; k0 < CC; k0 += 8) {
        const bool hasNext = (k0 + 8 < CC);
        if (hasNext) {
            av = make_float4(0.f, 0.f, 0.f, 0.f);
            if (tokA >= 0) av = *(const float4*)(xt + (long long)tokA * CC + (k0 + 8) + ak);
            bv = *(const float4*)(B + (long long)(k0 + 8 + bk) * FF + n0 + bn);
        }

        mma_step_3xtf32(As[buf], Bs[buf], d, wm0, wn0, gid, tg);

        if (hasNext) {
            const int nb = buf ^ 1;
            As[nb][ak + 0][arow] = av.x; As[nb][ak + 1][arow] = av.y;
            As[nb][ak + 2][arow] = av.z; As[nb][ak + 3][arow] = av.w;
            *(float4*)&Bs[nb][bk][bn] = bv;
            __syncthreads();
            buf = nb;
        }
    }

    // epilogue: gelu + compact-row store (row guard vs cnt)
    #pragma unroll
    for (int i = 0; i < 4; i++) {
        const int r0 = m0 + wm0 + i * 16 + gid;
        const int r1 = r0 + 8;
        #pragma unroll
        for (int j = 0; j < 4; j++) {
            const int col = n0 + wn0 + j * 8 + 2 * tg;   // FF tile: always in-bounds
            if (r0 < cnt) {
                float v0 = d[i][j][0], v1 = d[i][j][1];
                v0 = 0.5f * v0 * (1.f + erff(v0 * 0.70710678118654752f));
                v1 = 0.5f * v1 * (1.f + erff(v1 * 0.70710678118654752f));
                Cout[(long long)r0 * FF + col] = v0;
                Cout[(long long)r0 * FF + col + 1] = v1;
            }
            if (r1 < cnt) {
                float v2 = d[i][j][2], v3 = d[i][j][3];
                v2 = 0.5f * v2 * (1.f + erff(v2 * 0.70710678118654752f));
                v3 = 0.5f * v3 * (1.f + erff(v3 * 0.70710678118654752f));
                Cout[(long long)r1 * FF + col] = v2;
                Cout[(long long)r1 * FF + col + 1] = v3;
            }
        }
    }
}

// ---------------- MoE down-proj: 3xTF32, compact in, token-scatter out ------
// grid: x = CC/128 (2), y = NN/128 (16), z = expert.
__global__ __launch_bounds__(256)
void moe_down_tf32_k(const float* __restrict__ hbuf, const float* __restrict__ w2,
                     float* __restrict__ feo)
{
    const int e = blockIdx.z;
    const int cnt = g_cnt[e];
    const int m0 = blockIdx.y * 128;
    if (m0 >= cnt) return;
    const int n0 = blockIdx.x * 128;

    const float* A = hbuf + (long long)e * NN * FF;
    const float* B = w2 + (long long)e * FF * CC;

    __shared__ float As[2][8][132];
    __shared__ float Bs[2][8][132];
    __shared__ int toks[128];

    const int tid = threadIdx.x;
    if (tid < 128) toks[tid] = (m0 + tid < cnt) ? g_list[e * NN + m0 + tid] : -1;
    __syncthreads();

    const int wid = tid >> 5, lane = tid & 31;
    const int wm0 = (wid >> 2) * 64;
    const int wn0 = (wid & 3) * 32;
    const int gid = lane >> 2, tg = lane & 3;

    const int arow = tid >> 1, ak = (tid & 1) * 4;
    const int bk = tid >> 5, bn = (tid & 31) * 4;
    const bool rowOK = (m0 + arow < cnt);

    float d[4][4][4];
    #pragma unroll
    for (int i = 0; i < 4; i++)
        #pragma unroll
        for (int j = 0; j < 4; j++)
            #pragma unroll
            for (int r = 0; r < 4; r++) d[i][j][r] = 0.f;

    float4 av, bv;
    av = make_float4(0.f, 0.f, 0.f, 0.f);
    if (rowOK) av = *(const float4*)(A + (long long)(m0 + arow) * FF + ak);
    bv = *(const float4*)(B + (long long)bk * CC + n0 + bn);
    As[0][ak + 0][arow] = av.x; As[0][ak + 1][arow] = av.y;
    As[0][ak + 2][arow] = av.z; As[0][ak + 3][arow] = av.w;
    *(float4*)&Bs[0][bk][bn] = bv;
    __syncthreads();

    int buf = 0;
    for (int k0 = 0; k0 < FF; k0 += 8) {
        const bool hasNext = (k0 + 8 < FF);
        if (hasNext) {
            av = make_float4(0.f, 0.f, 0.f, 0.f);
            if (rowOK) av = *(const float4*)(A + (long long)(m0 + arow) * FF + (k0 + 8) + ak);
            bv = *(const float4*)(B + (long long)(k0 + 8 + bk) * CC + n0 + bn);
        }

        mma_step_3xtf32(As[buf], Bs[buf], d, wm0, wn0, gid, tg);

        if (hasNext) {
            const int nb = buf ^ 1;
            As[nb][ak + 0][arow] = av.x; As[nb][ak + 1][arow] = av.y;
            As[nb][ak + 2][arow] = av.z; As[nb][ak + 3][arow] = av.w;
            *(float4*)&Bs[nb][bk][bn] = bv;
            __syncthreads();
            buf = nb;
        }
    }

    // epilogue: scatter by token into full_expert_outputs
    #pragma unroll
    for (int i = 0; i < 4; i++) {
        const int t0 = toks[wm0 + i * 16 + gid];
        const int t1 = toks[wm0 + i * 16 + 8 + gid];
        #pragma unroll
        for (int j = 0; j < 4; j++) {
            const int col = n0 + wn0 + j * 8 + 2 * tg;   // CC tile: always in-bounds
            if (t0 >= 0) {
                float* dst = feo + ((long long)t0 * EE + e) * CC + col;
                dst[0] = d[i][j][0];
                dst[1] = d[i][j][1];
            }
            if (t1 >= 0) {
                float* dst = feo + ((long long)t1 * EE + e) * CC + col;
                dst[0] = d[i][j][2];
                dst[1] = d[i][j][3];
            }
        }
    }
}

// ---------------- causal attention, 1 thread per query, flash-style ---------
__global__ __launch_bounds__(64)
void attn_k(const float* __restrict__ q, const float* __restrict__ k,
            const float* __restrict__ v, float* __restrict__ ao)
{
    const int bh = blockIdx.y, b = bh / HH, h = bh % HH;
    const int qi = blockIdx.x * 64 + threadIdx.x;
    const float scale = 0.17677669529663687f;  // 1/sqrt(32)

    float qr[DD], acc[DD];
    const long long qoff = ((long long)(b * TT + qi)) * CC + h * DD;
    #pragma unroll
    for (int d = 0; d < DD; d += 4) {
        float4 t4 = *(const float4*)(q + qoff + d);
        qr[d] = t4.x; qr[d + 1] = t4.y; qr[d + 2] = t4.z; qr[d + 3] = t4.w;
    }
    #pragma unroll
    for (int d = 0; d < DD; d++) acc[d] = 0.f;

    float m = -1e30f, l = 0.f;
    __shared__ float Ks[64][DD], Vs[64][DD];

    const int kend = blockIdx.x * 64 + 64;
    for (int t0 = 0; t0 < kend; t0 += 64) {
        __syncthreads();
        const long long koff = ((long long)(b * TT + t0 + threadIdx.x)) * CC + h * DD;
        #pragma unroll
        for (int i = 0; i < DD; i += 4) {
            float4 k4 = *(const float4*)(k + koff + i);
            Ks[threadIdx.x][i] = k4.x; Ks[threadIdx.x][i + 1] = k4.y;
            Ks[threadIdx.x][i + 2] = k4.z; Ks[threadIdx.x][i + 3] = k4.w;
            float4 v4 = *(const float4*)(v + koff + i);
            Vs[threadIdx.x][i] = v4.x; Vs[threadIdx.x][i + 1] = v4.y;
            Vs[threadIdx.x][i + 2] = v4.z; Vs[threadIdx.x][i + 3] = v4.w;
        }
        __syncthreads();

        const int jend = min(64, qi - t0 + 1);
        for (int j = 0; j < jend; j++) {
            float kx[DD];
            #pragma unroll
            for (int i = 0; i < DD; i += 4) {
                float4 t4 = *(const float4*)&Ks[j][i];
                kx[i] = t4.x; kx[i + 1] = t4.y; kx[i + 2] = t4.z; kx[i + 3] = t4.w;
            }
            float s0 = 0.f, s1 = 0.f, s2 = 0.f, s3 = 0.f;
            #pragma unroll
            for (int d = 0; d < DD; d += 4) {
                s0 = fmaf(qr[d],     kx[d],     s0);
                s1 = fmaf(qr[d + 1], kx[d + 1], s1);
                s2 = fmaf(qr[d + 2], kx[d + 2], s2);
                s3 = fmaf(qr[d + 3], kx[d + 3], s3);
            }
            float s = ((s0 + s1) + (s2 + s3)) * scale;
            float nm = fmaxf(m, s);
            float es = __expf(s - nm);
            float sc = __expf(m - nm);
            l = l * sc + es;
            #pragma unroll
            for (int d = 0; d < DD; d += 4) {
                float4 t4 = *(const float4*)&Vs[j][d];
                acc[d]     = fmaf(es, t4.x, acc[d]     * sc);
                acc[d + 1] = fmaf(es, t4.y, acc[d + 1] * sc);
                acc[d + 2] = fmaf(es, t4.z, acc[d + 2] * sc);
                acc[d + 3] = fmaf(es, t4.w, acc[d + 3] * sc);
            }
            m = nm;
        }
    }

    const float inv = 1.f / l;
    #pragma unroll
    for (int d = 0; d < DD; d++) ao[qoff + d] = acc[d] * inv;
}

// ---------------- gating: normalize, threshold, top-16 fallback, softmax ----
__global__ void gate_k(const float* __restrict__ raw, const float* __restrict__ xnorm,
                       const float* __restrict__ snorm, const float* __restrict__ gates,
                       float* __restrict__ out_pre, float* __restrict__ out_am,
                       float* __restrict__ rw)
{
    const int token = blockIdx.x * 8 + threadIdx.y;
    const int e = threadIdx.x;

    float xn = fmaxf(xnorm[token], 1e-12f);
    float logit = raw[token * EE + e] / (xn * snorm[e]);
    float sig = 1.f / (1.f + __expf(-gates[e]));
    float pre = logit - sig;
    float gated = fmaxf(pre, 0.f);

    unsigned ballot = __ballot_sync(0xffffffffu, gated > 0.f);
    float am;
    if (ballot == 0u) {
        int rank = 0;
        #pragma unroll
        for (int j = 0; j < EE; j++) {
            float lj = __shfl_sync(0xffffffffu, logit, j);
            rank += (lj > logit) || (lj == logit && j < e);
        }
        am = (rank < (EE / 2)) ? 1.f : 0.f;
    } else {
        am = (gated > 0.f) ? 1.f : 0.f;
    }

    float gl = (am > 0.f) ? gated : NEGF;
    float mx = gl;
    #pragma unroll
    for (int o = 16; o > 0; o >>= 1) mx = fmaxf(mx, __shfl_xor_sync(0xffffffffu, mx, o));
    float ev = __expf(gl - mx);
    float sm = ev;
    #pragma unroll
    for (int o = 16; o > 0; o >>= 1) sm += __shfl_xor_sync(0xffffffffu, sm, o);

    out_pre[token * EE + e] = pre;
    out_am [token * EE + e] = am;
    rw     [token * EE + e] = ev / sm;
}

// ---------------- zero expert counters ----------------
__global__ void zero_cnt_k()
{
    if (threadIdx.x < EE) g_cnt[threadIdx.x] = 0;
}

// ---------------- zero ONLY inactive (t,e) rows of feo ----------------------
__global__ void zero_inactive_k(const float* __restrict__ am, float4* __restrict__ feo)
{
    const int idx = blockIdx.x;                 // t*EE + e
    if (am[idx] > 0.f) return;
    feo[(long long)idx * (CC / 4) + threadIdx.x] = make_float4(0.f, 0.f, 0.f, 0.f);
}

// ---------------- build per-expert active token lists ------------------------
__global__ void compact_k(const float* __restrict__ am)
{
    int idx = blockIdx.x * blockDim.x + threadIdx.x;   // over NN*EE
    int t = idx / EE, e = idx % EE;
    if (am[idx] > 0.f) {
        int i = atomicAdd(&g_cnt[e], 1);
        g_list[e * NN + i] = t;
    }
}

// ---------------- moe combine + residual (skip exactly-zero weights) --------
__global__ void moe_reduce_k(const float* __restrict__ feo, const float* __restrict__ rw,
                             const float* __restrict__ hs, float* __restrict__ hsf)
{
    const int t = blockIdx.x, c = threadIdx.x;
    __shared__ float w[EE];
    if (c < EE) w[c] = rw[t * EE + c];
    __syncthreads();
    const float* f = feo + (long long)t * EE * CC + c;
    float s = 0.f;
    for (int e = 0; e < EE; e++) {
        float we = w[e];
        if (we != 0.f) s = fmaf(we, f[(long long)e * CC], s);
    }
    hsf[t * CC + c] = hs[t * CC + c] + s;
}

// ---------------- host-side launch helper ----------------
static void sgemm_al(const float* A, const float* B, float* C, const float* Src,
                     int M, int Nn, int K, int lda, int ldb, int ldc, int flags)
{
    dim3 grid((Nn + 127) / 128, (M + 127) / 128, 1);
    if (flags == 2)
        sgemm_k<2, true><<<grid, 256>>>(A, B, C, Src, M, Nn, K, lda, ldb, ldc);
    else
        sgemm_k<0, true><<<grid, 256>>>(A, B, C, Src, M, Nn, K, lda, ldb, ldc);
}

extern "C" void kernel_launch(void* const* d_in, const int* in_sizes, int n_in,
                              void* d_out, int out_size)
{
    const int*   ids   = (const int*)  d_in[0];
    const float* emb   = (const float*)d_in[1];
    const float* wq    = (const float*)d_in[2];
    const float* wk    = (const float*)d_in[3];
    const float* wv    = (const float*)d_in[4];
    const float* wo    = (const float*)d_in[5];
    const float* ln1w  = (const float*)d_in[6];
    const float* ln1b  = (const float*)d_in[7];
    const float* ln2w  = (const float*)d_in[8];
    const float* ln2b  = (const float*)d_in[9];
    const float* sim   = (const float*)d_in[10];
    const float* gates = (const float*)d_in[11];
    const float* w1    = (const float*)d_in[12];
    const float* w2    = (const float*)d_in[13];
    const float* lmh   = (const float*)d_in[14];

    float* out        = (float*)d_out;
    float* out_logits = out;                                       // [B,T,V]
    float* out_feo    = out_logits + (long long)BB * TT * VV;      // [N,E,C]
    float* out_pre    = out_feo    + (long long)NN * EE * CC;      // [N,E]
    float* out_am     = out_pre    + (long long)NN * EE;           // [N,E]

    float *hs, *x, *q, *k, *v, *ao, *xt, *hsf, *lraw, *rw, *xn, *sn, *hbuf;
    cudaGetSymbolAddress((void**)&hs,   g_hs);
    cudaGetSymbolAddress((void**)&x,    g_x);
    cudaGetSymbolAddress((void**)&q,    g_q);
    cudaGetSymbolAddress((void**)&k,    g_k);
    cudaGetSymbolAddress((void**)&v,    g_v);
    cudaGetSymbolAddress((void**)&ao,   g_ao);
    cudaGetSymbolAddress((void**)&xt,   g_xt);
    cudaGetSymbolAddress((void**)&hsf,  g_hsf);
    cudaGetSymbolAddress((void**)&lraw, g_lraw);
    cudaGetSymbolAddress((void**)&rw,   g_rw);
    cudaGetSymbolAddress((void**)&xn,   g_xnorm);
    cudaGetSymbolAddress((void**)&sn,   g_snorm);
    cudaGetSymbolAddress((void**)&hbuf, g_h);

    // 1. embed
    embed_k<<<NN, CC>>>(ids, emb, hs);
    // 2. ln1
    ln_k<<<NN, CC>>>(hs, ln1w, ln1b, x, nullptr);
    // 3. q/k/v projections (fp32: feed gate-critical path via residual stream)
    sgemm_al(x, wq, q, nullptr, NN, CC, CC, CC, CC, CC, 0);
    sgemm_al(x, wk, k, nullptr, NN, CC, CC, CC, CC, CC, 0);
    sgemm_al(x, wv, v, nullptr, NN, CC, CC, CC, CC, CC, 0);
    // 4. causal attention
    attn_k<<<dim3(TT / 64, BB * HH), 64>>>(q, k, v, ao);
    // 5. hs += ao @ wo
    sgemm_al(ao, wo, hs, hs, NN, CC, CC, CC, CC, CC, 2);
    // 6. ln2 (+ row norms for cosine gate)
    ln_k<<<NN, CC>>>(hs, ln2w, ln2b, xt, xn);
    // 7. sim column norms
    snorm_k<<<EE, CC>>>(sim, sn);
    // 8. raw gate logits = xt @ sim (fp32 — mask-critical)
    sgemm_al(xt, sim, lraw, nullptr, NN, EE, CC, CC, EE, EE, 0);
    // 9. gate: pre / activation_mask / routing weights
    gate_k<<<NN / 8, dim3(32, 8)>>>(lraw, xn, sn, gates, out_pre, out_am, rw);
    // 10. compaction lists + zero only inactive feo rows
    zero_cnt_k<<<1, 32>>>();
    compact_k<<<(NN * EE) / 256, 256>>>(out_am);
    zero_inactive_k<<<NN * EE, 64>>>(out_am, (float4*)out_feo);
    // 11. expert up-proj + gelu (3xTF32 tensor cores)
    moe_up_tf32_k<<<dim3(FF / 128, NN / 128, EE), 256>>>(xt, w1, hbuf);
    // 12. expert down-proj, token-scatter (3xTF32 tensor cores)
    moe_down_tf32_k<<<dim3(CC / 128, NN / 128, EE), 256>>>(hbuf, w2, out_feo);
    // 13. moe combine + residual
    moe_reduce_k<<<NN, CC>>>(out_feo, rw, hs, hsf);
    // 14. lm head: 3xTF32 tensor-core GEMM
    lmhead_tf32_k<<<dim3((VV + 127) / 128, NN / 128), 256>>>(hsf, lmh, out_logits,
                                                            NN, VV, CC, VV);
}

// round 8
// speedup vs baseline: 1.2384x; 1.2384x over previous
#include <cuda_runtime.h>
#include <cuda_bf16.h>
#include <math.h>
#include <stdint.h>

// ---------------- problem constants ----------------
#define BB 2
#define TT 1024
#define CC 256
#define FF 1024
#define EE 32
#define VV 50257
#define HH 8
#define DD 32
#define NN 2048   // B*T
#define C3 768    // 3*CC packed qkv width

#define NEGF (-3.3895313892515355e38f)   // -finfo(bf16).max

// ---------------- scratch (__device__ globals; no allocations allowed) ------
__device__ float g_hs  [NN * CC];
__device__ float g_x   [NN * CC];
__device__ float g_qkv [NN * C3];
__device__ float g_wqkv[CC * C3];
__device__ float g_ao  [NN * CC];
__device__ float g_xt  [NN * CC];
__device__ float g_hsf [NN * CC];
__device__ float g_lraw[NN * EE];
__device__ float g_rw  [NN * EE];
__device__ float g_xnorm[NN];
__device__ float g_snorm[EE];
__device__ int   g_cnt [EE];
__device__ int   g_list[EE * NN];
__device__ float g_h[(size_t)EE * NN * FF];   // expert hidden acts (compact rows)

// ---------------- embedding gather ----------------
__global__ void embed_k(const int* __restrict__ ids, const float* __restrict__ emb,
                        float* __restrict__ hs)
{
    int row = blockIdx.x, tid = threadIdx.x;
    hs[row * CC + tid] = emb[(long long)ids[row] * CC + tid];
}

// ---------------- pack wq|wk|wv into one 256x768 B matrix -------------------
__global__ void pack_wqkv_k(const float* __restrict__ wq, const float* __restrict__ wk,
                            const float* __restrict__ wv, float* __restrict__ wqkv)
{
    int k = blockIdx.x, c = threadIdx.x;
    wqkv[k * C3 + c]       = wq[k * CC + c];
    wqkv[k * C3 + CC + c]  = wk[k * CC + c];
    wqkv[k * C3 + 2*CC + c]= wv[k * CC + c];
}

// ---------------- layernorm (block per row, 256 threads = C) ----------------
__global__ void ln_k(const float* __restrict__ x, const float* __restrict__ w,
                     const float* __restrict__ b, float* __restrict__ y,
                     float* __restrict__ norms)
{
    int row = blockIdx.x, tid = threadIdx.x;
    __shared__ float red[CC];
    float v = x[row * CC + tid];

    red[tid] = v; __syncthreads();
    for (int s = CC / 2; s > 0; s >>= 1) {
        if (tid < s) red[tid] += red[tid + s];
        __syncthreads();
    }
    float mu = red[0] / CC;
    __syncthreads();

    float d = v - mu;
    red[tid] = d * d; __syncthreads();
    for (int s = CC / 2; s > 0; s >>= 1) {
        if (tid < s) red[tid] += red[tid + s];
        __syncthreads();
    }
    float var = red[0] / CC;
    __syncthreads();

    float ys = d * rsqrtf(var + 1e-5f) * w[tid] + b[tid];
    y[row * CC + tid] = ys;

    if (norms) {
        red[tid] = ys * ys; __syncthreads();
        for (int s = CC / 2; s > 0; s >>= 1) {
            if (tid < s) red[tid] += red[tid + s];
            __syncthreads();
        }
        if (tid == 0) norms[row] = sqrtf(red[0]);
    }
}

// ---------------- sim_matrix column norms ----------------
__global__ void snorm_k(const float* __restrict__ sim, float* __restrict__ sn)
{
    int e = blockIdx.x, tid = threadIdx.x;
    __shared__ float red[CC];
    float v = sim[(long long)tid * EE + e];
    red[tid] = v * v; __syncthreads();
    for (int s = CC / 2; s > 0; s >>= 1) {
        if (tid < s) red[tid] += red[tid + s];
        __syncthreads();
    }
    if (tid == 0) sn[e] = fmaxf(sqrtf(red[0]), 1e-12f);
}

// ---------------- generic fp32 SGEMM, 128x128x8, double-buffered ------------
// (precision-critical path: fused QKV, attn-out, gate logits)
template <int FLAGS, bool ALIGNED_B>
__global__ __launch_bounds__(256, 2)
void sgemm_k(const float* __restrict__ A, const float* __restrict__ B,
             float* __restrict__ Cout, const float* __restrict__ Src,
             int M, int Nn, int K, int lda, int ldb, int ldc)
{
    __shared__ float As[2][8][128];
    __shared__ float Bs[2][8][132];

    const int tid = threadIdx.x;
    const int tx = tid & 15, ty = tid >> 4;
    const int m0 = blockIdx.y * 128, n0 = blockIdx.x * 128;

    const int arow = tid >> 1, ak = (tid & 1) * 4;
    const int bk = tid >> 5, bn = (tid & 31) * 4;
    const bool aOK = (m0 + arow < M);
    const int nb0 = n0 + bn;
    const bool bVec = (nb0 + 3 < Nn);

    float acc[8][8];
    #pragma unroll
    for (int i = 0; i < 8; i++)
        #pragma unroll
        for (int j = 0; j < 8; j++) acc[i][j] = 0.f;

    float4 av;
    float  bv0, bv1, bv2, bv3;

    {
        av = make_float4(0.f, 0.f, 0.f, 0.f);
        if (aOK) av = *(const float4*)(A + (long long)(m0 + arow) * lda + ak);
        const long long brow = (long long)bk * ldb;
        if (ALIGNED_B && bVec) {
            float4 b4 = *(const float4*)(B + brow + nb0);
            bv0 = b4.x; bv1 = b4.y; bv2 = b4.z; bv3 = b4.w;
        } else {
            bv0 = (nb0 + 0 < Nn) ? B[brow + nb0 + 0] : 0.f;
            bv1 = (nb0 + 1 < Nn) ? B[brow + nb0 + 1] : 0.f;
            bv2 = (nb0 + 2 < Nn) ? B[brow + nb0 + 2] : 0.f;
            bv3 = (nb0 + 3 < Nn) ? B[brow + nb0 + 3] : 0.f;
        }
    }
    As[0][ak + 0][arow] = av.x;
    As[0][ak + 1][arow] = av.y;
    As[0][ak + 2][arow] = av.z;
    As[0][ak + 3][arow] = av.w;
    Bs[0][bk][bn + 0] = bv0;
    Bs[0][bk][bn + 1] = bv1;
    Bs[0][bk][bn + 2] = bv2;
    Bs[0][bk][bn + 3] = bv3;
    __syncthreads();

    int buf = 0;
    for (int k0 = 0; k0 < K; k0 += 8) {
        const bool hasNext = (k0 + 8 < K);
        if (hasNext) {
            av = make_float4(0.f, 0.f, 0.f, 0.f);
            if (aOK) av = *(const float4*)(A + (long long)(m0 + arow) * lda + (k0 + 8) + ak);
            const long long brow = (long long)(k0 + 8 + bk) * ldb;
            if (ALIGNED_B && bVec) {
                float4 b4 = *(const float4*)(B + brow + nb0);
                bv0 = b4.x; bv1 = b4.y; bv2 = b4.z; bv3 = b4.w;
            } else {
                bv0 = (nb0 + 0 < Nn) ? B[brow + nb0 + 0] : 0.f;
                bv1 = (nb0 + 1 < Nn) ? B[brow + nb0 + 1] : 0.f;
                bv2 = (nb0 + 2 < Nn) ? B[brow + nb0 + 2] : 0.f;
                bv3 = (nb0 + 3 < Nn) ? B[brow + nb0 + 3] : 0.f;
            }
        }

        #pragma unroll
        for (int kk = 0; kk < 8; kk++) {
            float a[8], bfr[8];
            #pragma unroll
            for (int i = 0; i < 8; i++) a[i] = As[buf][kk][ty * 8 + i];
            #pragma unroll
            for (int j = 0; j < 8; j++) bfr[j] = Bs[buf][kk][tx * 8 + j];
            #pragma unroll
            for (int i = 0; i < 8; i++)
                #pragma unroll
                for (int j = 0; j < 8; j++)
                    acc[i][j] = fmaf(a[i], bfr[j], acc[i][j]);
        }

        if (hasNext) {
            const int nb = buf ^ 1;
            As[nb][ak + 0][arow] = av.x;
            As[nb][ak + 1][arow] = av.y;
            As[nb][ak + 2][arow] = av.z;
            As[nb][ak + 3][arow] = av.w;
            Bs[nb][bk][bn + 0] = bv0;
            Bs[nb][bk][bn + 1] = bv1;
            Bs[nb][bk][bn + 2] = bv2;
            Bs[nb][bk][bn + 3] = bv3;
            __syncthreads();
            buf = nb;
        }
    }

    const int r0 = m0 + ty * 8, c0 = n0 + tx * 8;
    #pragma unroll
    for (int i = 0; i < 8; i++) {
        int r = r0 + i;
        if (r >= M) continue;
        #pragma unroll
        for (int j = 0; j < 8; j++) {
            int c = c0 + j;
            if (c >= Nn) continue;
            float v = acc[i][j];
            if (FLAGS & 2) v += Src[(long long)r * ldc + c];
            Cout[(long long)r * ldc + c] = v;
        }
    }
}

// ---------------- 3xBF16 mma building blocks --------------------------------
// Emulated fp32: hi = bf16(x), lo = bf16(x-hi); D += Ahi*Bhi + Ahi*Blo + Alo*Bhi.
// Block 128x128, 8 warps (2m x 4n), warp tile 64x32, m16n8k16 atoms (K=16/step).
__device__ __forceinline__ void bsplit(float x, __nv_bfloat16& h, __nv_bfloat16& l)
{
    h = __float2bfloat16_rn(x);
    l = __float2bfloat16_rn(x - __bfloat162float(h));
}
__device__ __forceinline__ uint32_t pack2(__nv_bfloat16 e0, __nv_bfloat16 e1)
{
    __nv_bfloat162 t = __halves2bfloat162(e0, e1);   // e0 -> low 16 bits (lower k)
    return *reinterpret_cast<uint32_t*>(&t);
}

#define MMA_BF16(D, A0, A1, A2, A3, B0, B1)                                     \
    asm volatile("mma.sync.aligned.m16n8k16.row.col.f32.bf16.bf16.f32 "         \
                 "{%0,%1,%2,%3}, {%4,%5,%6,%7}, {%8,%9}, {%0,%1,%2,%3};"        \
                 : "+f"((D)[0]), "+f"((D)[1]), "+f"((D)[2]), "+f"((D)[3])       \
                 : "r"(A0), "r"(A1), "r"(A2), "r"(A3), "r"(B0), "r"(B1))

// One 16-deep K-step of the 64x32 warp tile.
// m16n8k16 fragments: a0=(r,k01) a1=(r+8,k01) a2=(r,k89) a3=(r+8,k89);
// b0=(k01,c) b1=(k89,c); D layout identical to the validated m16n8k8 kernel.
__device__ __forceinline__ void mma_step_3xbf16(
    const float (*As)[132], const float (*Bs)[132],
    float d[4][4][4], int wm0, int wn0, int gid, int tg)
{
    const int k0 = 2 * tg, k2 = 2 * tg + 8;
    uint32_t ahi[4][4], alo[4][4];
    #pragma unroll
    for (int i = 0; i < 4; i++) {
        const int r0 = wm0 + i * 16 + gid, r1 = r0 + 8;
        __nv_bfloat16 h0, l0, h1, l1;
        bsplit(As[k0][r0], h0, l0); bsplit(As[k0 + 1][r0], h1, l1);
        ahi[i][0] = pack2(h0, h1); alo[i][0] = pack2(l0, l1);
        bsplit(As[k0][r1], h0, l0); bsplit(As[k0 + 1][r1], h1, l1);
        ahi[i][1] = pack2(h0, h1); alo[i][1] = pack2(l0, l1);
        bsplit(As[k2][r0], h0, l0); bsplit(As[k2 + 1][r0], h1, l1);
        ahi[i][2] = pack2(h0, h1); alo[i][2] = pack2(l0, l1);
        bsplit(As[k2][r1], h0, l0); bsplit(As[k2 + 1][r1], h1, l1);
        ahi[i][3] = pack2(h0, h1); alo[i][3] = pack2(l0, l1);
    }
    #pragma unroll
    for (int j = 0; j < 4; j++) {
        const int c = wn0 + j * 8 + gid;
        __nv_bfloat16 h0, l0, h1, l1, h2, l2, h3, l3;
        bsplit(Bs[k0][c], h0, l0); bsplit(Bs[k0 + 1][c], h1, l1);
        bsplit(Bs[k2][c], h2, l2); bsplit(Bs[k2 + 1][c], h3, l3);
        const uint32_t bh0 = pack2(h0, h1), bl0 = pack2(l0, l1);
        const uint32_t bh1 = pack2(h2, h3), bl1 = pack2(l2, l3);
        #pragma unroll
        for (int i = 0; i < 4; i++) {
            MMA_BF16(d[i][j], ahi[i][0], ahi[i][1], ahi[i][2], ahi[i][3], bh0, bh1);
            MMA_BF16(d[i][j], ahi[i][0], ahi[i][1], ahi[i][2], ahi[i][3], bl0, bl1);
            MMA_BF16(d[i][j], alo[i][0], alo[i][1], alo[i][2], alo[i][3], bh0, bh1);
        }
    }
}

// ---------------- LM head: 3xBF16 tensor-core GEMM --------------------------
__global__ __launch_bounds__(256)
void lmhead_bf16_k(const float* __restrict__ A, const float* __restrict__ B,
                   float* __restrict__ Cout, int M, int Nn, int K, int ldb)
{
    __shared__ float As[2][16][132];
    __shared__ float Bs[2][16][132];

    const int tid = threadIdx.x;
    const int wid = tid >> 5, lane = tid & 31;
    const int wm0 = (wid >> 2) * 64;
    const int wn0 = (wid & 3) * 32;
    const int gid = lane >> 2, tg = lane & 3;
    const int m0 = blockIdx.y * 128, n0 = blockIdx.x * 128;

    const int arow = tid >> 1, akb = (tid & 1) * 8;
    const int bk = tid >> 5, bn = (tid & 31) * 4;
    const int nb0 = n0 + bn;

    float d[4][4][4];
    #pragma unroll
    for (int i = 0; i < 4; i++)
        #pragma unroll
        for (int j = 0; j < 4; j++)
            #pragma unroll
            for (int r = 0; r < 4; r++) d[i][j][r] = 0.f;

    float4 av0, av1;
    float bv[2][4];

    // prologue (M = 2048 divisible by 128: A rows always valid)
    av0 = *(const float4*)(A + (long long)(m0 + arow) * K + akb);
    av1 = *(const float4*)(A + (long long)(m0 + arow) * K + akb + 4);
    #pragma unroll
    for (int h = 0; h < 2; h++) {
        const long long brow = (long long)(bk + h * 8) * ldb;
        #pragma unroll
        for (int t = 0; t < 4; t++)
            bv[h][t] = (nb0 + t < Nn) ? B[brow + nb0 + t] : 0.f;
    }
    As[0][akb + 0][arow] = av0.x; As[0][akb + 1][arow] = av0.y;
    As[0][akb + 2][arow] = av0.z; As[0][akb + 3][arow] = av0.w;
    As[0][akb + 4][arow] = av1.x; As[0][akb + 5][arow] = av1.y;
    As[0][akb + 6][arow] = av1.z; As[0][akb + 7][arow] = av1.w;
    #pragma unroll
    for (int h = 0; h < 2; h++)
        #pragma unroll
        for (int t = 0; t < 4; t++) Bs[0][bk + h * 8][bn + t] = bv[h][t];
    __syncthreads();

    int buf = 0;
    for (int k0 = 0; k0 < K; k0 += 16) {
        const bool hasNext = (k0 + 16 < K);
        if (hasNext) {
            av0 = *(const float4*)(A + (long long)(m0 + arow) * K + (k0 + 16) + akb);
            av1 = *(const float4*)(A + (long long)(m0 + arow) * K + (k0 + 16) + akb + 4);
            #pragma unroll
            for (int h = 0; h < 2; h++) {
                const long long brow = (long long)(k0 + 16 + bk + h * 8) * ldb;
                #pragma unroll
                for (int t = 0; t < 4; t++)
                    bv[h][t] = (nb0 + t < Nn) ? B[brow + nb0 + t] : 0.f;
            }
        }

        mma_step_3xbf16(As[buf], Bs[buf], d, wm0, wn0, gid, tg);

        if (hasNext) {
            const int nb = buf ^ 1;
            As[nb][akb + 0][arow] = av0.x; As[nb][akb + 1][arow] = av0.y;
            As[nb][akb + 2][arow] = av0.z; As[nb][akb + 3][arow] = av0.w;
            As[nb][akb + 4][arow] = av1.x; As[nb][akb + 5][arow] = av1.y;
            As[nb][akb + 6][arow] = av1.z; As[nb][akb + 7][arow] = av1.w;
            #pragma unroll
            for (int h = 0; h < 2; h++)
                #pragma unroll
                for (int t = 0; t < 4; t++) Bs[nb][bk + h * 8][bn + t] = bv[h][t];
            __syncthreads();
            buf = nb;
        }
    }

    #pragma unroll
    for (int i = 0; i < 4; i++) {
        const int row = m0 + wm0 + i * 16 + gid;
        #pragma unroll
        for (int j = 0; j < 4; j++) {
            const int col = n0 + wn0 + j * 8 + 2 * tg;
            if (col < Nn) {
                Cout[(long long)row * ldb + col] = d[i][j][0];
                Cout[(long long)(row + 8) * ldb + col] = d[i][j][2];
            }
            if (col + 1 < Nn) {
                Cout[(long long)row * ldb + col + 1] = d[i][j][1];
                Cout[(long long)(row + 8) * ldb + col + 1] = d[i][j][3];
            }
        }
    }
}

// ---------------- MoE up-proj: 3xBF16, gathered rows, gelu epilogue ---------
// grid: x = FF/128 (8), y = NN/128 (16), z = expert.
__global__ __launch_bounds__(256)
void moe_up_bf16_k(const float* __restrict__ xt, const float* __restrict__ w1,
                   float* __restrict__ hbuf)
{
    const int e = blockIdx.z;
    const int cnt = g_cnt[e];
    const int m0 = blockIdx.y * 128;
    if (m0 >= cnt) return;
    const int n0 = blockIdx.x * 128;

    const float* B = w1 + (long long)e * CC * FF;
    float* Cout = hbuf + (long long)e * NN * FF;

    __shared__ float As[2][16][132];
    __shared__ float Bs[2][16][132];
    __shared__ int toks[128];

    const int tid = threadIdx.x;
    if (tid < 128) toks[tid] = (m0 + tid < cnt) ? g_list[e * NN + m0 + tid] : -1;
    __syncthreads();

    const int wid = tid >> 5, lane = tid & 31;
    const int wm0 = (wid >> 2) * 64;
    const int wn0 = (wid & 3) * 32;
    const int gid = lane >> 2, tg = lane & 3;

    const int arow = tid >> 1, akb = (tid & 1) * 8;
    const int bk = tid >> 5, bn = (tid & 31) * 4;
    const int tokA = toks[arow];

    float d[4][4][4];
    #pragma unroll
    for (int i = 0; i < 4; i++)
        #pragma unroll
        for (int j = 0; j < 4; j++)
            #pragma unroll
            for (int r = 0; r < 4; r++) d[i][j][r] = 0.f;

    float4 av0, av1, bv0, bv1;
    av0 = make_float4(0.f, 0.f, 0.f, 0.f); av1 = av0;
    if (tokA >= 0) {
        av0 = *(const float4*)(xt + (long long)tokA * CC + akb);
        av1 = *(const float4*)(xt + (long long)tokA * CC + akb + 4);
    }
    bv0 = *(const float4*)(B + (long long)bk * FF + n0 + bn);
    bv1 = *(const float4*)(B + (long long)(bk + 8) * FF + n0 + bn);
    As[0][akb + 0][arow] = av0.x; As[0][akb + 1][arow] = av0.y;
    As[0][akb + 2][arow] = av0.z; As[0][akb + 3][arow] = av0.w;
    As[0][akb + 4][arow] = av1.x; As[0][akb + 5][arow] = av1.y;
    As[0][akb + 6][arow] = av1.z; As[0][akb + 7][arow] = av1.w;
    *(float4*)&Bs[0][bk][bn] = bv0;
    *(float4*)&Bs[0][bk + 8][bn] = bv1;
    __syncthreads();

    int buf = 0;
    for (int k0 = 0; k0 < CC; k0 += 16) {
        const bool hasNext = (k0 + 16 < CC);
        if (hasNext) {
            av0 = make_float4(0.f, 0.f, 0.f, 0.f); av1 = av0;
            if (tokA >= 0) {
                av0 = *(const float4*)(xt + (long long)tokA * CC + (k0 + 16) + akb);
                av1 = *(const float4*)(xt + (long long)tokA * CC + (k0 + 16) + akb + 4);
            }
            bv0 = *(const float4*)(B + (long long)(k0 + 16 + bk) * FF + n0 + bn);
            bv1 = *(const float4*)(B + (long long)(k0 + 24 + bk) * FF + n0 + bn);
        }

        mma_step_3xbf16(As[buf], Bs[buf], d, wm0, wn0, gid, tg);

        if (hasNext) {
            const int nb = buf ^ 1;
            As[nb][akb + 0][arow] = av0.x; As[nb][akb + 1][arow] = av0.y;
            As[nb][akb + 2][arow] = av0.z; As[nb][akb + 3][arow] = av0.w;
            As[nb][akb + 4][arow] = av1.x; As[nb][akb + 5][arow] = av1.y;
            As[nb][akb + 6][arow] = av1.z; As[nb][akb + 7][arow] = av1.w;
            *(float4*)&Bs[nb][bk][bn] = bv0;
            *(float4*)&Bs[nb][bk + 8][bn] = bv1;
            __syncthreads();
            buf = nb;
        }
    }

    // epilogue: gelu + compact-row store (row guard vs cnt)
    #pragma unroll
    for (int i = 0; i < 4; i++) {
        const int r0 = m0 + wm0 + i * 16 + gid;
        const int r1 = r0 + 8;
        #pragma unroll
        for (int j = 0; j < 4; j++) {
            const int col = n0 + wn0 + j * 8 + 2 * tg;   // FF tile: in-bounds
            if (r0 < cnt) {
                float v0 = d[i][j][0], v1 = d[i][j][1];
                v0 = 0.5f * v0 * (1.f + erff(v0 * 0.70710678118654752f));
                v1 = 0.5f * v1 * (1.f + erff(v1 * 0.70710678118654752f));
                Cout[(long long)r0 * FF + col] = v0;
                Cout[(long long)r0 * FF + col + 1] = v1;
            }
            if (r1 < cnt) {
                float v2 = d[i][j][2], v3 = d[i][j][3];
                v2 = 0.5f * v2 * (1.f + erff(v2 * 0.70710678118654752f));
                v3 = 0.5f * v3 * (1.f + erff(v3 * 0.70710678118654752f));
                Cout[(long long)r1 * FF + col] = v2;
                Cout[(long long)r1 * FF + col + 1] = v3;
            }
        }
    }
}

// ---------------- MoE down-proj: 3xBF16, compact in, token-scatter out ------
// grid: x = CC/128 (2), y = NN/128 (16), z = expert.
__global__ __launch_bounds__(256)
void moe_down_bf16_k(const float* __restrict__ hbuf, const float* __restrict__ w2,
                     float* __restrict__ feo)
{
    const int e = blockIdx.z;
    const int cnt = g_cnt[e];
    const int m0 = blockIdx.y * 128;
    if (m0 >= cnt) return;
    const int n0 = blockIdx.x * 128;

    const float* A = hbuf + (long long)e * NN * FF;
    const float* B = w2 + (long long)e * FF * CC;

    __shared__ float As[2][16][132];
    __shared__ float Bs[2][16][132];
    __shared__ int toks[128];

    const int tid = threadIdx.x;
    if (tid < 128) toks[tid] = (m0 + tid < cnt) ? g_list[e * NN + m0 + tid] : -1;
    __syncthreads();

    const int wid = tid >> 5, lane = tid & 31;
    const int wm0 = (wid >> 2) * 64;
    const int wn0 = (wid & 3) * 32;
    const int gid = lane >> 2, tg = lane & 3;

    const int arow = tid >> 1, akb = (tid & 1) * 8;
    const int bk = tid >> 5, bn = (tid & 31) * 4;
    const bool rowOK = (m0 + arow < cnt);

    float d[4][4][4];
    #pragma unroll
    for (int i = 0; i < 4; i++)
        #pragma unroll
        for (int j = 0; j < 4; j++)
            #pragma unroll
            for (int r = 0; r < 4; r++) d[i][j][r] = 0.f;

    float4 av0, av1, bv0, bv1;
    av0 = make_float4(0.f, 0.f, 0.f, 0.f); av1 = av0;
    if (rowOK) {
        av0 = *(const float4*)(A + (long long)(m0 + arow) * FF + akb);
        av1 = *(const float4*)(A + (long long)(m0 + arow) * FF + akb + 4);
    }
    bv0 = *(const float4*)(B + (long long)bk * CC + n0 + bn);
    bv1 = *(const float4*)(B + (long long)(bk + 8) * CC + n0 + bn);
    As[0][akb + 0][arow] = av0.x; As[0][akb + 1][arow] = av0.y;
    As[0][akb + 2][arow] = av0.z; As[0][akb + 3][arow] = av0.w;
    As[0][akb + 4][arow] = av1.x; As[0][akb + 5][arow] = av1.y;
    As[0][akb + 6][arow] = av1.z; As[0][akb + 7][arow] = av1.w;
    *(float4*)&Bs[0][bk][bn] = bv0;
    *(float4*)&Bs[0][bk + 8][bn] = bv1;
    __syncthreads();

    int buf = 0;
    for (int k0 = 0; k0 < FF; k0 += 16) {
        const bool hasNext = (k0 + 16 < FF);
        if (hasNext) {
            av0 = make_float4(0.f, 0.f, 0.f, 0.f); av1 = av0;
            if (rowOK) {
                av0 = *(const float4*)(A + (long long)(m0 + arow) * FF + (k0 + 16) + akb);
                av1 = *(const float4*)(A + (long long)(m0 + arow) * FF + (k0 + 16) + akb + 4);
            }
            bv0 = *(const float4*)(B + (long long)(k0 + 16 + bk) * CC + n0 + bn);
            bv1 = *(const float4*)(B + (long long)(k0 + 24 + bk) * CC + n0 + bn);
        }

        mma_step_3xbf16(As[buf], Bs[buf], d, wm0, wn0, gid, tg);

        if (hasNext) {
            const int nb = buf ^ 1;
            As[nb][akb + 0][arow] = av0.x; As[nb][akb + 1][arow] = av0.y;
            As[nb][akb + 2][arow] = av0.z; As[nb][akb + 3][arow] = av0.w;
            As[nb][akb + 4][arow] = av1.x; As[nb][akb + 5][arow] = av1.y;
            As[nb][akb + 6][arow] = av1.z; As[nb][akb + 7][arow] = av1.w;
            *(float4*)&Bs[nb][bk][bn] = bv0;
            *(float4*)&Bs[nb][bk + 8][bn] = bv1;
            __syncthreads();
            buf = nb;
        }
    }

    // epilogue: scatter by token into full_expert_outputs
    #pragma unroll
    for (int i = 0; i < 4; i++) {
        const int t0 = toks[wm0 + i * 16 + gid];
        const int t1 = toks[wm0 + i * 16 + 8 + gid];
        #pragma unroll
        for (int j = 0; j < 4; j++) {
            const int col = n0 + wn0 + j * 8 + 2 * tg;   // CC tile: in-bounds
            if (t0 >= 0) {
                float* dst = feo + ((long long)t0 * EE + e) * CC + col;
                dst[0] = d[i][j][0];
                dst[1] = d[i][j][1];
            }
            if (t1 >= 0) {
                float* dst = feo + ((long long)t1 * EE + e) * CC + col;
                dst[0] = d[i][j][2];
                dst[1] = d[i][j][3];
            }
        }
    }
}

// ---------------- causal attention over packed qkv [N, 768] -----------------
__global__ __launch_bounds__(64)
void attn_k(const float* __restrict__ qkv, float* __restrict__ ao)
{
    const int bh = blockIdx.y, b = bh / HH, h = bh % HH;
    const int qi = blockIdx.x * 64 + threadIdx.x;
    const float scale = 0.17677669529663687f;  // 1/sqrt(32)

    float qr[DD], acc[DD];
    const long long qoff = ((long long)(b * TT + qi)) * C3 + h * DD;
    #pragma unroll
    for (int d = 0; d < DD; d += 4) {
        float4 t4 = *(const float4*)(qkv + qoff + d);
        qr[d] = t4.x; qr[d + 1] = t4.y; qr[d + 2] = t4.z; qr[d + 3] = t4.w;
    }
    #pragma unroll
    for (int d = 0; d < DD; d++) acc[d] = 0.f;

    float m = -1e30f, l = 0.f;
    __shared__ float Ks[64][DD], Vs[64][DD];

    const int kend = blockIdx.x * 64 + 64;
    for (int t0 = 0; t0 < kend; t0 += 64) {
        __syncthreads();
        const long long koff = ((long long)(b * TT + t0 + threadIdx.x)) * C3 + CC + h * DD;
        #pragma unroll
        for (int i = 0; i < DD; i += 4) {
            float4 k4 = *(const float4*)(qkv + koff + i);
            Ks[threadIdx.x][i] = k4.x; Ks[threadIdx.x][i + 1] = k4.y;
            Ks[threadIdx.x][i + 2] = k4.z; Ks[threadIdx.x][i + 3] = k4.w;
            float4 v4 = *(const float4*)(qkv + koff + CC + i);
            Vs[threadIdx.x][i] = v4.x; Vs[threadIdx.x][i + 1] = v4.y;
            Vs[threadIdx.x][i + 2] = v4.z; Vs[threadIdx.x][i + 3] = v4.w;
        }
        __syncthreads();

        const int jend = min(64, qi - t0 + 1);
        for (int j = 0; j < jend; j++) {
            float kx[DD];
            #pragma unroll
            for (int i = 0; i < DD; i += 4) {
                float4 t4 = *(const float4*)&Ks[j][i];
                kx[i] = t4.x; kx[i + 1] = t4.y; kx[i + 2] = t4.z; kx[i + 3] = t4.w;
            }
            float s0 = 0.f, s1 = 0.f, s2 = 0.f, s3 = 0.f;
            #pragma unroll
            for (int d = 0; d < DD; d += 4) {
                s0 = fmaf(qr[d],     kx[d],     s0);
                s1 = fmaf(qr[d + 1], kx[d + 1], s1);
                s2 = fmaf(qr[d + 2], kx[d + 2], s2);
                s3 = fmaf(qr[d + 3], kx[d + 3], s3);
            }
            float s = ((s0 + s1) + (s2 + s3)) * scale;
            float nm = fmaxf(m, s);
            float es = __expf(s - nm);
            float sc = __expf(m - nm);
            l = l * sc + es;
            #pragma unroll
            for (int d = 0; d < DD; d += 4) {
                float4 t4 = *(const float4*)&Vs[j][d];
                acc[d]     = fmaf(es, t4.x, acc[d]     * sc);
                acc[d + 1] = fmaf(es, t4.y, acc[d + 1] * sc);
                acc[d + 2] = fmaf(es, t4.z, acc[d + 2] * sc);
                acc[d + 3] = fmaf(es, t4.w, acc[d + 3] * sc);
            }
            m = nm;
        }
    }

    const float inv = 1.f / l;
    const long long aoff = ((long long)(b * TT + qi)) * CC + h * DD;
    #pragma unroll
    for (int d = 0; d < DD; d++) ao[aoff + d] = acc[d] * inv;
}

// ---------------- gating: normalize, threshold, top-16 fallback, softmax ----
__global__ void gate_k(const float* __restrict__ raw, const float* __restrict__ xnorm,
                       const float* __restrict__ snorm, const float* __restrict__ gates,
                       float* __restrict__ out_pre, float* __restrict__ out_am,
                       float* __restrict__ rw)
{
    const int token = blockIdx.x * 8 + threadIdx.y;
    const int e = threadIdx.x;

    float xn = fmaxf(xnorm[token], 1e-12f);
    float logit = raw[token * EE + e] / (xn * snorm[e]);
    float sig = 1.f / (1.f + __expf(-gates[e]));
    float pre = logit - sig;
    float gated = fmaxf(pre, 0.f);

    unsigned ballot = __ballot_sync(0xffffffffu, gated > 0.f);
    float am;
    if (ballot == 0u) {
        int rank = 0;
        #pragma unroll
        for (int j = 0; j < EE; j++) {
            float lj = __shfl_sync(0xffffffffu, logit, j);
            rank += (lj > logit) || (lj == logit && j < e);
        }
        am = (rank < (EE / 2)) ? 1.f : 0.f;
    } else {
        am = (gated > 0.f) ? 1.f : 0.f;
    }

    float gl = (am > 0.f) ? gated : NEGF;
    float mx = gl;
    #pragma unroll
    for (int o = 16; o > 0; o >>= 1) mx = fmaxf(mx, __shfl_xor_sync(0xffffffffu, mx, o));
    float ev = __expf(gl - mx);
    float sm = ev;
    #pragma unroll
    for (int o = 16; o > 0; o >>= 1) sm += __shfl_xor_sync(0xffffffffu, sm, o);

    out_pre[token * EE + e] = pre;
    out_am [token * EE + e] = am;
    rw     [token * EE + e] = ev / sm;
}

// ---------------- zero expert counters ----------------
__global__ void zero_cnt_k()
{
    if (threadIdx.x < EE) g_cnt[threadIdx.x] = 0;
}

// ---------------- zero ONLY inactive (t,e) rows of feo ----------------------
__global__ void zero_inactive_k(const float* __restrict__ am, float4* __restrict__ feo)
{
    const int idx = blockIdx.x;                 // t*EE + e
    if (am[idx] > 0.f) return;
    feo[(long long)idx * (CC / 4) + threadIdx.x] = make_float4(0.f, 0.f, 0.f, 0.f);
}

// ---------------- build per-expert active token lists ------------------------
__global__ void compact_k(const float* __restrict__ am)
{
    int idx = blockIdx.x * blockDim.x + threadIdx.x;   // over NN*EE
    int t = idx / EE, e = idx % EE;
    if (am[idx] > 0.f) {
        int i = atomicAdd(&g_cnt[e], 1);
        g_list[e * NN + i] = t;
    }
}

// ---------------- moe combine + residual (skip exactly-zero weights) --------
__global__ void moe_reduce_k(const float* __restrict__ feo, const float* __restrict__ rw,
                             const float* __restrict__ hs, float* __restrict__ hsf)
{
    const int t = blockIdx.x, c = threadIdx.x;
    __shared__ float w[EE];
    if (c < EE) w[c] = rw[t * EE + c];
    __syncthreads();
    const float* f = feo + (long long)t * EE * CC + c;
    float s = 0.f;
    for (int e = 0; e < EE; e++) {
        float we = w[e];
        if (we != 0.f) s = fmaf(we, f[(long long)e * CC], s);
    }
    hsf[t * CC + c] = hs[t * CC + c] + s;
}

// ---------------- host-side launch helper ----------------
static void sgemm_al(const float* A, const float* B, float* C, const float* Src,
                     int M, int Nn, int K, int lda, int ldb, int ldc, int flags)
{
    dim3 grid((Nn + 127) / 128, (M + 127) / 128, 1);
    if (flags == 2)
        sgemm_k<2, true><<<grid, 256>>>(A, B, C, Src, M, Nn, K, lda, ldb, ldc);
    else
        sgemm_k<0, true><<<grid, 256>>>(A, B, C, Src, M, Nn, K, lda, ldb, ldc);
}

extern "C" void kernel_launch(void* const* d_in, const int* in_sizes, int n_in,
                              void* d_out, int out_size)
{
    const int*   ids   = (const int*)  d_in[0];
    const float* emb   = (const float*)d_in[1];
    const float* wq    = (const float*)d_in[2];
    const float* wk    = (const float*)d_in[3];
    const float* wv    = (const float*)d_in[4];
    const float* wo    = (const float*)d_in[5];
    const float* ln1w  = (const float*)d_in[6];
    const float* ln1b  = (const float*)d_in[7];
    const float* ln2w  = (const float*)d_in[8];
    const float* ln2b  = (const float*)d_in[9];
    const float* sim   = (const float*)d_in[10];
    const float* gates = (const float*)d_in[11];
    const float* w1    = (const float*)d_in[12];
    const float* w2    = (const float*)d_in[13];
    const float* lmh   = (const float*)d_in[14];

    float* out        = (float*)d_out;
    float* out_logits = out;                                       // [B,T,V]
    float* out_feo    = out_logits + (long long)BB * TT * VV;      // [N,E,C]
    float* out_pre    = out_feo    + (long long)NN * EE * CC;      // [N,E]
    float* out_am     = out_pre    + (long long)NN * EE;           // [N,E]

    float *hs, *x, *qkv, *wqkv, *ao, *xt, *hsf, *lraw, *rw, *xn, *sn, *hbuf;
    cudaGetSymbolAddress((void**)&hs,   g_hs);
    cudaGetSymbolAddress((void**)&x,    g_x);
    cudaGetSymbolAddress((void**)&qkv,  g_qkv);
    cudaGetSymbolAddress((void**)&wqkv, g_wqkv);
    cudaGetSymbolAddress((void**)&ao,   g_ao);
    cudaGetSymbolAddress((void**)&xt,   g_xt);
    cudaGetSymbolAddress((void**)&hsf,  g_hsf);
    cudaGetSymbolAddress((void**)&lraw, g_lraw);
    cudaGetSymbolAddress((void**)&rw,   g_rw);
    cudaGetSymbolAddress((void**)&xn,   g_xnorm);
    cudaGetSymbolAddress((void**)&sn,   g_snorm);
    cudaGetSymbolAddress((void**)&hbuf, g_h);

    // 1. embed + ln1 + pack qkv weights
    embed_k<<<NN, CC>>>(ids, emb, hs);
    ln_k<<<NN, CC>>>(hs, ln1w, ln1b, x, nullptr);
    pack_wqkv_k<<<CC, CC>>>(wq, wk, wv, wqkv);
    // 2. fused q|k|v projection (fp32, 96 blocks)
    sgemm_al(x, wqkv, qkv, nullptr, NN, C3, CC, CC, C3, C3, 0);
    // 3. causal attention on packed layout
    attn_k<<<dim3(TT / 64, BB * HH), 64>>>(qkv, ao);
    // 4. hs += ao @ wo (fp32)
    sgemm_al(ao, wo, hs, hs, NN, CC, CC, CC, CC, CC, 2);
    // 5. ln2 (+ row norms for cosine gate)
    ln_k<<<NN, CC>>>(hs, ln2w, ln2b, xt, xn);
    // 6. sim column norms + raw gate logits (fp32 — mask-critical)
    snorm_k<<<EE, CC>>>(sim, sn);
    sgemm_al(xt, sim, lraw, nullptr, NN, EE, CC, CC, EE, EE, 0);
    // 7. gate: pre / activation_mask / routing weights
    gate_k<<<NN / 8, dim3(32, 8)>>>(lraw, xn, sn, gates, out_pre, out_am, rw);
    // 8. compaction lists + zero only inactive feo rows
    zero_cnt_k<<<1, 32>>>();
    compact_k<<<(NN * EE) / 256, 256>>>(out_am);
    zero_inactive_k<<<NN * EE, 64>>>(out_am, (float4*)out_feo);
    // 9. expert up-proj + gelu (3xBF16 tensor cores)
    moe_up_bf16_k<<<dim3(FF / 128, NN / 128, EE), 256>>>(xt, w1, hbuf);
    // 10. expert down-proj, token-scatter (3xBF16 tensor cores)
    moe_down_bf16_k<<<dim3(CC / 128, NN / 128, EE), 256>>>(hbuf, w2, out_feo);
    // 11. moe combine + residual
    moe_reduce_k<<<NN, CC>>>(out_feo, rw, hs, hsf);
    // 12. lm head (3xBF16 tensor cores)
    lmhead_bf16_k<<<dim3((VV + 127) / 128, NN / 128), 256>>>(hsf, lmh, out_logits,
                                                             NN, VV, CC, VV);
}

// round 14
// speedup vs baseline: 1.5361x; 1.2404x over previous
#include <cuda_runtime.h>
#include <cuda_bf16.h>
#include <math.h>
#include <stdint.h>

// ---------------- problem constants ----------------
#define BB 2
#define TT 1024
#define CC 256
#define FF 1024
#define EE 32
#define VV 50257
#define HH 8
#define DD 32
#define NN 2048   // B*T
#define C3 768    // 3*CC packed qkv width
#define PD 136    // smem row pad (uint32) -> bank = 8*tg + gid, conflict-free reads

#define NEGF (-3.3895313892515355e38f)   // -finfo(bf16).max

// ---------------- scratch (__device__ globals; no allocations allowed) ------
__device__ float g_hs  [NN * CC];
__device__ float g_x   [NN * CC];
__device__ float g_qkv [NN * C3];
__device__ float g_wqkv[CC * C3];
__device__ float g_ao  [NN * CC];
__device__ float g_xt  [NN * CC];
__device__ float g_hsf [NN * CC];
__device__ float g_lraw[NN * EE];
__device__ float g_rw  [NN * EE];
__device__ float g_xnorm[NN];
__device__ float g_snorm[EE];
__device__ int   g_cnt [EE];
__device__ int   g_list[EE * NN];
__device__ float g_h[(size_t)EE * NN * FF];   // expert hidden acts (compact rows)

// ---------------- fused embedding gather + ln1 ------------------------------
__global__ void embed_ln1_k(const int* __restrict__ ids, const float* __restrict__ emb,
                            const float* __restrict__ w, const float* __restrict__ b,
                            float* __restrict__ hs, float* __restrict__ x)
{
    int row = blockIdx.x, tid = threadIdx.x;
    __shared__ float red[CC];
    float v = emb[(long long)ids[row] * CC + tid];
    hs[row * CC + tid] = v;

    red[tid] = v; __syncthreads();
    for (int s = CC / 2; s > 0; s >>= 1) {
        if (tid < s) red[tid] += red[tid + s];
        __syncthreads();
    }
    float mu = red[0] / CC;
    __syncthreads();

    float d = v - mu;
    red[tid] = d * d; __syncthreads();
    for (int s = CC / 2; s > 0; s >>= 1) {
        if (tid < s) red[tid] += red[tid + s];
        __syncthreads();
    }
    float var = red[0] / CC;

    x[row * CC + tid] = d * rsqrtf(var + 1e-5f) * w[tid] + b[tid];
}

// ---------------- pack wq|wk|wv into one 256x768 B matrix -------------------
__global__ void pack_wqkv_k(const float* __restrict__ wq, const float* __restrict__ wk,
                            const float* __restrict__ wv, float* __restrict__ wqkv)
{
    int k = blockIdx.x, c = threadIdx.x;
    wqkv[k * C3 + c]        = wq[k * CC + c];
    wqkv[k * C3 + CC + c]   = wk[k * CC + c];
    wqkv[k * C3 + 2*CC + c] = wv[k * CC + c];
}

// ---------------- layernorm (block per row, 256 threads = C) ----------------
__global__ void ln_k(const float* __restrict__ x, const float* __restrict__ w,
                     const float* __restrict__ b, float* __restrict__ y,
                     float* __restrict__ norms)
{
    int row = blockIdx.x, tid = threadIdx.x;
    __shared__ float red[CC];
    float v = x[row * CC + tid];

    red[tid] = v; __syncthreads();
    for (int s = CC / 2; s > 0; s >>= 1) {
        if (tid < s) red[tid] += red[tid + s];
        __syncthreads();
    }
    float mu = red[0] / CC;
    __syncthreads();

    float d = v - mu;
    red[tid] = d * d; __syncthreads();
    for (int s = CC / 2; s > 0; s >>= 1) {
        if (tid < s) red[tid] += red[tid + s];
        __syncthreads();
    }
    float var = red[0] / CC;
    __syncthreads();

    float ys = d * rsqrtf(var + 1e-5f) * w[tid] + b[tid];
    y[row * CC + tid] = ys;

    if (norms) {
        red[tid] = ys * ys; __syncthreads();
        for (int s = CC / 2; s > 0; s >>= 1) {
            if (tid < s) red[tid] += red[tid + s];
            __syncthreads();
        }
        if (tid == 0) norms[row] = sqrtf(red[0]);
    }
}

// ---------------- sim_matrix column norms ----------------
__global__ void snorm_k(const float* __restrict__ sim, float* __restrict__ sn)
{
    int e = blockIdx.x, tid = threadIdx.x;
    __shared__ float red[CC];
    float v = sim[(long long)tid * EE + e];
    red[tid] = v * v; __syncthreads();
    for (int s = CC / 2; s > 0; s >>= 1) {
        if (tid < s) red[tid] += red[tid + s];
        __syncthreads();
    }
    if (tid == 0) sn[e] = fmaxf(sqrtf(red[0]), 1e-12f);
}

// ---------------- generic fp32 SGEMM, 128x128x8, double-buffered ------------
template <int FLAGS, bool ALIGNED_B>
__global__ __launch_bounds__(256, 2)
void sgemm_k(const float* __restrict__ A, const float* __restrict__ B,
             float* __restrict__ Cout, const float* __restrict__ Src,
             int M, int Nn, int K, int lda, int ldb, int ldc)
{
    __shared__ float As[2][8][128];
    __shared__ float Bs[2][8][132];

    const int tid = threadIdx.x;
    const int tx = tid & 15, ty = tid >> 4;
    const int m0 = blockIdx.y * 128, n0 = blockIdx.x * 128;

    const int arow = tid >> 1, ak = (tid & 1) * 4;
    const int bk = tid >> 5, bn = (tid & 31) * 4;
    const bool aOK = (m0 + arow < M);
    const int nb0 = n0 + bn;
    const bool bVec = (nb0 + 3 < Nn);

    float acc[8][8];
    #pragma unroll
    for (int i = 0; i < 8; i++)
        #pragma unroll
        for (int j = 0; j < 8; j++) acc[i][j] = 0.f;

    float4 av;
    float  bv0, bv1, bv2, bv3;

    {
        av = make_float4(0.f, 0.f, 0.f, 0.f);
        if (aOK) av = *(const float4*)(A + (long long)(m0 + arow) * lda + ak);
        const long long brow = (long long)bk * ldb;
        if (ALIGNED_B && bVec) {
            float4 b4 = *(const float4*)(B + brow + nb0);
            bv0 = b4.x; bv1 = b4.y; bv2 = b4.z; bv3 = b4.w;
        } else {
            bv0 = (nb0 + 0 < Nn) ? B[brow + nb0 + 0] : 0.f;
            bv1 = (nb0 + 1 < Nn) ? B[brow + nb0 + 1] : 0.f;
            bv2 = (nb0 + 2 < Nn) ? B[brow + nb0 + 2] : 0.f;
            bv3 = (nb0 + 3 < Nn) ? B[brow + nb0 + 3] : 0.f;
        }
    }
    As[0][ak + 0][arow] = av.x;
    As[0][ak + 1][arow] = av.y;
    As[0][ak + 2][arow] = av.z;
    As[0][ak + 3][arow] = av.w;
    Bs[0][bk][bn + 0] = bv0;
    Bs[0][bk][bn + 1] = bv1;
    Bs[0][bk][bn + 2] = bv2;
    Bs[0][bk][bn + 3] = bv3;
    __syncthreads();

    int buf = 0;
    for (int k0 = 0; k0 < K; k0 += 8) {
        const bool hasNext = (k0 + 8 < K);
        if (hasNext) {
            av = make_float4(0.f, 0.f, 0.f, 0.f);
            if (aOK) av = *(const float4*)(A + (long long)(m0 + arow) * lda + (k0 + 8) + ak);
            const long long brow = (long long)(k0 + 8 + bk) * ldb;
            if (ALIGNED_B && bVec) {
                float4 b4 = *(const float4*)(B + brow + nb0);
                bv0 = b4.x; bv1 = b4.y; bv2 = b4.z; bv3 = b4.w;
            } else {
                bv0 = (nb0 + 0 < Nn) ? B[brow + nb0 + 0] : 0.f;
                bv1 = (nb0 + 1 < Nn) ? B[brow + nb0 + 1] : 0.f;
                bv2 = (nb0 + 2 < Nn) ? B[brow + nb0 + 2] : 0.f;
                bv3 = (nb0 + 3 < Nn) ? B[brow + nb0 + 3] : 0.f;
            }
        }

        #pragma unroll
        for (int kk = 0; kk < 8; kk++) {
            float a[8], bfr[8];
            #pragma unroll
            for (int i = 0; i < 8; i++) a[i] = As[buf][kk][ty * 8 + i];
            #pragma unroll
            for (int j = 0; j < 8; j++) bfr[j] = Bs[buf][kk][tx * 8 + j];
            #pragma unroll
            for (int i = 0; i < 8; i++)
                #pragma unroll
                for (int j = 0; j < 8; j++)
                    acc[i][j] = fmaf(a[i], bfr[j], acc[i][j]);
        }

        if (hasNext) {
            const int nb = buf ^ 1;
            As[nb][ak + 0][arow] = av.x;
            As[nb][ak + 1][arow] = av.y;
            As[nb][ak + 2][arow] = av.z;
            As[nb][ak + 3][arow] = av.w;
            Bs[nb][bk][bn + 0] = bv0;
            Bs[nb][bk][bn + 1] = bv1;
            Bs[nb][bk][bn + 2] = bv2;
            Bs[nb][bk][bn + 3] = bv3;
            __syncthreads();
            buf = nb;
        }
    }

    const int r0 = m0 + ty * 8, c0 = n0 + tx * 8;
    #pragma unroll
    for (int i = 0; i < 8; i++) {
        int r = r0 + i;
        if (r >= M) continue;
        #pragma unroll
        for (int j = 0; j < 8; j++) {
            int c = c0 + j;
            if (c >= Nn) continue;
            float v = acc[i][j];
            if (FLAGS & 2) v += Src[(long long)r * ldc + c];
            Cout[(long long)r * ldc + c] = v;
        }
    }
}

// ---------------- 3xBF16 with pre-split smem --------------------------------
__device__ __forceinline__ void bsplit2(float x0, float x1, uint32_t& hi, uint32_t& lo)
{
    __nv_bfloat16 h0 = __float2bfloat16_rn(x0);
    __nv_bfloat16 h1 = __float2bfloat16_rn(x1);
    __nv_bfloat16 l0 = __float2bfloat16_rn(x0 - __bfloat162float(h0));
    __nv_bfloat16 l1 = __float2bfloat16_rn(x1 - __bfloat162float(h1));
    __nv_bfloat162 th = __halves2bfloat162(h0, h1);   // x0 -> low 16 (lower k)
    __nv_bfloat162 tl = __halves2bfloat162(l0, l1);
    hi = *reinterpret_cast<uint32_t*>(&th);
    lo = *reinterpret_cast<uint32_t*>(&tl);
}

#define MMA_BF16(D, A0, A1, A2, A3, B0, B1)                                     \
    asm volatile("mma.sync.aligned.m16n8k16.row.col.f32.bf16.bf16.f32 "         \
                 "{%0,%1,%2,%3}, {%4,%5,%6,%7}, {%8,%9}, {%0,%1,%2,%3};"        \
                 : "+f"((D)[0]), "+f"((D)[1]), "+f"((D)[2]), "+f"((D)[3])       \
                 : "r"(A0), "r"(A1), "r"(A2), "r"(A3), "r"(B0), "r"(B1))

__device__ __forceinline__ void mma_step_pre(
    const uint32_t (*Ah)[PD], const uint32_t (*Al)[PD],
    const uint32_t (*Bh)[PD], const uint32_t (*Bl)[PD],
    float d[4][4][4], int wm0, int wn0, int gid, int tg)
{
    uint32_t ah[4][4], al[4][4];
    #pragma unroll
    for (int i = 0; i < 4; i++) {
        const int r0 = wm0 + i * 16 + gid, r1 = r0 + 8;
        ah[i][0] = Ah[tg][r0];     ah[i][1] = Ah[tg][r1];
        ah[i][2] = Ah[tg + 4][r0]; ah[i][3] = Ah[tg + 4][r1];
        al[i][0] = Al[tg][r0];     al[i][1] = Al[tg][r1];
        al[i][2] = Al[tg + 4][r0]; al[i][3] = Al[tg + 4][r1];
    }
    #pragma unroll
    for (int j = 0; j < 4; j++) {
        const int c = wn0 + j * 8 + gid;
        const uint32_t bh0 = Bh[tg][c], bh1 = Bh[tg + 4][c];
        const uint32_t bl0 = Bl[tg][c], bl1 = Bl[tg + 4][c];
        #pragma unroll
        for (int i = 0; i < 4; i++) {
            MMA_BF16(d[i][j], ah[i][0], ah[i][1], ah[i][2], ah[i][3], bh0, bh1);
            MMA_BF16(d[i][j], ah[i][0], ah[i][1], ah[i][2], ah[i][3], bl0, bl1);
            MMA_BF16(d[i][j], al[i][0], al[i][1], al[i][2], al[i][3], bh0, bh1);
        }
    }
}

__device__ __forceinline__ void store_a_stage(
    uint32_t (*Ah)[PD], uint32_t (*Al)[PD], int akb2, int arow,
    const float4& v0, const float4& v1)
{
    uint32_t h, l;
    bsplit2(v0.x, v0.y, h, l); Ah[akb2 + 0][arow] = h; Al[akb2 + 0][arow] = l;
    bsplit2(v0.z, v0.w, h, l); Ah[akb2 + 1][arow] = h; Al[akb2 + 1][arow] = l;
    bsplit2(v1.x, v1.y, h, l); Ah[akb2 + 2][arow] = h; Al[akb2 + 2][arow] = l;
    bsplit2(v1.z, v1.w, h, l); Ah[akb2 + 3][arow] = h; Al[akb2 + 3][arow] = l;
}

__device__ __forceinline__ void store_b_stage(
    uint32_t (*Bh)[PD], uint32_t (*Bl)[PD], int bkk, int bn,
    const float* r0, const float* r1)
{
    #pragma unroll
    for (int t = 0; t < 4; t++) {
        uint32_t h, l;
        bsplit2(r0[t], r1[t], h, l);
        Bh[bkk][bn + t] = h; Bl[bkk][bn + t] = l;
    }
}

// ---------------- LM head: 3xBF16 pre-split ---------------------------------
// grid: x = M tiles (16), y = N tiles (393). x-fastest raster -> 16 consecutive
// blocks share one 128-col B tile (L2-resident) across all M.
__global__ __launch_bounds__(256, 2)
void lmhead_bf16_k(const float* __restrict__ A, const float* __restrict__ B,
                   float* __restrict__ Cout, int M, int Nn, int K, int ldb)
{
    __shared__ uint32_t Ah[2][8][PD], Al[2][8][PD];
    __shared__ uint32_t Bh[2][8][PD], Bl[2][8][PD];

    const int tid = threadIdx.x;
    const int wid = tid >> 5, lane = tid & 31;
    const int wm0 = (wid >> 2) * 64;
    const int wn0 = (wid & 3) * 32;
    const int gid = lane >> 2, tg = lane & 3;
    const int m0 = blockIdx.x * 128, n0 = blockIdx.y * 128;

    const int arow = tid >> 1, akb = (tid & 1) * 8, akb2 = (tid & 1) * 4;
    const int bkk = tid >> 5, bn = (tid & 31) * 4;
    const int nb0 = n0 + bn;

    float d[4][4][4];
    #pragma unroll
    for (int i = 0; i < 4; i++)
        #pragma unroll
        for (int j = 0; j < 4; j++)
            #pragma unroll
            for (int r = 0; r < 4; r++) d[i][j][r] = 0.f;

    float4 av0, av1;
    float br0[4], br1[4];

    av0 = *(const float4*)(A + (long long)(m0 + arow) * K + akb);
    av1 = *(const float4*)(A + (long long)(m0 + arow) * K + akb + 4);
    {
        const long long r0off = (long long)(2 * bkk) * ldb;
        const long long r1off = (long long)(2 * bkk + 1) * ldb;
        #pragma unroll
        for (int t = 0; t < 4; t++) {
            br0[t] = (nb0 + t < Nn) ? B[r0off + nb0 + t] : 0.f;
            br1[t] = (nb0 + t < Nn) ? B[r1off + nb0 + t] : 0.f;
        }
    }
    store_a_stage(Ah[0], Al[0], akb2, arow, av0, av1);
    store_b_stage(Bh[0], Bl[0], bkk, bn, br0, br1);
    __syncthreads();

    int buf = 0;
    for (int k0 = 0; k0 < K; k0 += 16) {
        const bool hasNext = (k0 + 16 < K);
        if (hasNext) {
            av0 = *(const float4*)(A + (long long)(m0 + arow) * K + (k0 + 16) + akb);
            av1 = *(const float4*)(A + (long long)(m0 + arow) * K + (k0 + 16) + akb + 4);
            const long long r0off = (long long)(k0 + 16 + 2 * bkk) * ldb;
            const long long r1off = (long long)(k0 + 16 + 2 * bkk + 1) * ldb;
            #pragma unroll
            for (int t = 0; t < 4; t++) {
                br0[t] = (nb0 + t < Nn) ? B[r0off + nb0 + t] : 0.f;
                br1[t] = (nb0 + t < Nn) ? B[r1off + nb0 + t] : 0.f;
            }
        }

        mma_step_pre(Ah[buf], Al[buf], Bh[buf], Bl[buf], d, wm0, wn0, gid, tg);

        if (hasNext) {
            const int nb = buf ^ 1;
            store_a_stage(Ah[nb], Al[nb], akb2, arow, av0, av1);
            store_b_stage(Bh[nb], Bl[nb], bkk, bn, br0, br1);
            __syncthreads();
            buf = nb;
        }
    }

    #pragma unroll
    for (int i = 0; i < 4; i++) {
        const int row = m0 + wm0 + i * 16 + gid;
        #pragma unroll
        for (int j = 0; j < 4; j++) {
            const int col = n0 + wn0 + j * 8 + 2 * tg;
            if (col < Nn) {
                Cout[(long long)row * ldb + col] = d[i][j][0];
                Cout[(long long)(row + 8) * ldb + col] = d[i][j][2];
            }
            if (col + 1 < Nn) {
                Cout[(long long)row * ldb + col + 1] = d[i][j][1];
                Cout[(long long)(row + 8) * ldb + col + 1] = d[i][j][3];
            }
        }
    }
}

// ---------------- MoE up-proj: 3xBF16 pre-split, gathered rows, gelu --------
__global__ __launch_bounds__(256, 2)
void moe_up_bf16_k(const float* __restrict__ xt, const float* __restrict__ w1,
                   float* __restrict__ hbuf)
{
    const int e = blockIdx.z;
    const int cnt = g_cnt[e];
    const int m0 = blockIdx.y * 128;
    if (m0 >= cnt) return;
    const int n0 = blockIdx.x * 128;

    const float* B = w1 + (long long)e * CC * FF;
    float* Cout = hbuf + (long long)e * NN * FF;

    __shared__ uint32_t Ah[2][8][PD], Al[2][8][PD];
    __shared__ uint32_t Bh[2][8][PD], Bl[2][8][PD];
    __shared__ int toks[128];

    const int tid = threadIdx.x;
    if (tid < 128) toks[tid] = (m0 + tid < cnt) ? g_list[e * NN + m0 + tid] : -1;
    __syncthreads();

    const int wid = tid >> 5, lane = tid & 31;
    const int wm0 = (wid >> 2) * 64;
    const int wn0 = (wid & 3) * 32;
    const int gid = lane >> 2, tg = lane & 3;

    const int arow = tid >> 1, akb = (tid & 1) * 8, akb2 = (tid & 1) * 4;
    const int bkk = tid >> 5, bn = (tid & 31) * 4;
    const int tokA = toks[arow];

    float d[4][4][4];
    #pragma unroll
    for (int i = 0; i < 4; i++)
        #pragma unroll
        for (int j = 0; j < 4; j++)
            #pragma unroll
            for (int r = 0; r < 4; r++) d[i][j][r] = 0.f;

    float4 av0, av1, bv0, bv1;
    av0 = make_float4(0.f, 0.f, 0.f, 0.f); av1 = av0;
    if (tokA >= 0) {
        av0 = *(const float4*)(xt + (long long)tokA * CC + akb);
        av1 = *(const float4*)(xt + (long long)tokA * CC + akb + 4);
    }
    bv0 = *(const float4*)(B + (long long)(2 * bkk) * FF + n0 + bn);
    bv1 = *(const float4*)(B + (long long)(2 * bkk + 1) * FF + n0 + bn);
    store_a_stage(Ah[0], Al[0], akb2, arow, av0, av1);
    store_b_stage(Bh[0], Bl[0], bkk, bn, (const float*)&bv0, (const float*)&bv1);
    __syncthreads();

    int buf = 0;
    for (int k0 = 0; k0 < CC; k0 += 16) {
        const bool hasNext = (k0 + 16 < CC);
        if (hasNext) {
            av0 = make_float4(0.f, 0.f, 0.f, 0.f); av1 = av0;
            if (tokA >= 0) {
                av0 = *(const float4*)(xt + (long long)tokA * CC + (k0 + 16) + akb);
                av1 = *(const float4*)(xt + (long long)tokA * CC + (k0 + 16) + akb + 4);
            }
            bv0 = *(const float4*)(B + (long long)(k0 + 16 + 2 * bkk) * FF + n0 + bn);
            bv1 = *(const float4*)(B + (long long)(k0 + 16 + 2 * bkk + 1) * FF + n0 + bn);
        }

        mma_step_pre(Ah[buf], Al[buf], Bh[buf], Bl[buf], d, wm0, wn0, gid, tg);

        if (hasNext) {
            const int nb = buf ^ 1;
            store_a_stage(Ah[nb], Al[nb], akb2, arow, av0, av1);
            store_b_stage(Bh[nb], Bl[nb], bkk, bn, (const float*)&bv0, (const float*)&bv1);
            __syncthreads();
            buf = nb;
        }
    }

    // epilogue: gelu + compact-row store (row guard vs cnt)
    #pragma unroll
    for (int i = 0; i < 4; i++) {
        const int r0 = m0 + wm0 + i * 16 + gid;
        const int r1 = r0 + 8;
        #pragma unroll
        for (int j = 0; j < 4; j++) {
            const int col = n0 + wn0 + j * 8 + 2 * tg;   // FF tile: in-bounds
            if (r0 < cnt) {
                float v0 = d[i][j][0], v1 = d[i][j][1];
                v0 = 0.5f * v0 * (1.f + erff(v0 * 0.70710678118654752f));
                v1 = 0.5f * v1 * (1.f + erff(v1 * 0.70710678118654752f));
                Cout[(long long)r0 * FF + col] = v0;
                Cout[(long long)r0 * FF + col + 1] = v1;
            }
            if (r1 < cnt) {
                float v2 = d[i][j][2], v3 = d[i][j][3];
                v2 = 0.5f * v2 * (1.f + erff(v2 * 0.70710678118654752f));
                v3 = 0.5f * v3 * (1.f + erff(v3 * 0.70710678118654752f));
                Cout[(long long)r1 * FF + col] = v2;
                Cout[(long long)r1 * FF + col + 1] = v3;
            }
        }
    }
}

// ---------------- MoE down-proj: 3xBF16 pre-split, token-scatter out --------
__global__ __launch_bounds__(256, 2)
void moe_down_bf16_k(const float* __restrict__ hbuf, const float* __restrict__ w2,
                     float* __restrict__ feo)
{
    const int e = blockIdx.z;
    const int cnt = g_cnt[e];
    const int m0 = blockIdx.y * 128;
    if (m0 >= cnt) return;
    const int n0 = blockIdx.x * 128;

    const float* A = hbuf + (long long)e * NN * FF;
    const float* B = w2 + (long long)e * FF * CC;

    __shared__ uint32_t Ah[2][8][PD], Al[2][8][PD];
    __shared__ uint32_t Bh[2][8][PD], Bl[2][8][PD];
    __shared__ int toks[128];

    const int tid = threadIdx.x;
    if (tid < 128) toks[tid] = (m0 + tid < cnt) ? g_list[e * NN + m0 + tid] : -1;
    __syncthreads();

    const int wid = tid >> 5, lane = tid & 31;
    const int wm0 = (wid >> 2) * 64;
    const int wn0 = (wid & 3) * 32;
    const int gid = lane >> 2, tg = lane & 3;

    const int arow = tid >> 1, akb = (tid & 1) * 8, akb2 = (tid & 1) * 4;
    const int bkk = tid >> 5, bn = (tid & 31) * 4;
    const bool rowOK = (m0 + arow < cnt);

    float d[4][4][4];
    #pragma unroll
    for (int i = 0; i < 4; i++)
        #pragma unroll
        for (int j = 0; j < 4; j++)
            #pragma unroll
            for (int r = 0; r < 4; r++) d[i][j][r] = 0.f;

    float4 av0, av1, bv0, bv1;
    av0 = make_float4(0.f, 0.f, 0.f, 0.f); av1 = av0;
    if (rowOK) {
        av0 = *(const float4*)(A + (long long)(m0 + arow) * FF + akb);
        av1 = *(const float4*)(A + (long long)(m0 + arow) * FF + akb + 4);
    }
    bv0 = *(const float4*)(B + (long long)(2 * bkk) * CC + n0 + bn);
    bv1 = *(const float4*)(B + (long long)(2 * bkk + 1) * CC + n0 + bn);
    store_a_stage(Ah[0], Al[0], akb2, arow, av0, av1);
    store_b_stage(Bh[0], Bl[0], bkk, bn, (const float*)&bv0, (const float*)&bv1);
    __syncthreads();

    int buf = 0;
    for (int k0 = 0; k0 < FF; k0 += 16) {
        const bool hasNext = (k0 + 16 < FF);
        if (hasNext) {
            av0 = make_float4(0.f, 0.f, 0.f, 0.f); av1 = av0;
            if (rowOK) {
                av0 = *(const float4*)(A + (long long)(m0 + arow) * FF + (k0 + 16) + akb);
                av1 = *(const float4*)(A + (long long)(m0 + arow) * FF + (k0 + 16) + akb + 4);
            }
            bv0 = *(const float4*)(B + (long long)(k0 + 16 + 2 * bkk) * CC + n0 + bn);
            bv1 = *(const float4*)(B + (long long)(k0 + 16 + 2 * bkk + 1) * CC + n0 + bn);
        }

        mma_step_pre(Ah[buf], Al[buf], Bh[buf], Bl[buf], d, wm0, wn0, gid, tg);

        if (hasNext) {
            const int nb = buf ^ 1;
            store_a_stage(Ah[nb], Al[nb], akb2, arow, av0, av1);
            store_b_stage(Bh[nb], Bl[nb], bkk, bn, (const float*)&bv0, (const float*)&bv1);
            __syncthreads();
            buf = nb;
        }
    }

    // epilogue: scatter by token into full_expert_outputs
    #pragma unroll
    for (int i = 0; i < 4; i++) {
        const int t0 = toks[wm0 + i * 16 + gid];
        const int t1 = toks[wm0 + i * 16 + 8 + gid];
        #pragma unroll
        for (int j = 0; j < 4; j++) {
            const int col = n0 + wn0 + j * 8 + 2 * tg;   // CC tile: in-bounds
            if (t0 >= 0) {
                float* dst = feo + ((long long)t0 * EE + e) * CC + col;
                dst[0] = d[i][j][0];
                dst[1] = d[i][j][1];
            }
            if (t1 >= 0) {
                float* dst = feo + ((long long)t1 * EE + e) * CC + col;
                dst[0] = d[i][j][2];
                dst[1] = d[i][j][3];
            }
        }
    }
}

// ---------------- causal attention over packed qkv [N, 768] -----------------
__global__ __launch_bounds__(64)
void attn_k(const float* __restrict__ qkv, float* __restrict__ ao)
{
    const int bh = blockIdx.y, b = bh / HH, h = bh % HH;
    const int qi = blockIdx.x * 64 + threadIdx.x;
    const float scale = 0.17677669529663687f;  // 1/sqrt(32)

    float qr[DD], acc[DD];
    const long long qoff = ((long long)(b * TT + qi)) * C3 + h * DD;
    #pragma unroll
    for (int d = 0; d < DD; d += 4) {
        float4 t4 = *(const float4*)(qkv + qoff + d);
        qr[d] = t4.x; qr[d + 1] = t4.y; qr[d + 2] = t4.z; qr[d + 3] = t4.w;
    }
    #pragma unroll
    for (int d = 0; d < DD; d++) acc[d] = 0.f;

    float m = -1e30f, l = 0.f;
    __shared__ float Ks[64][DD], Vs[64][DD];

    const int kend = blockIdx.x * 64 + 64;
    for (int t0 = 0; t0 < kend; t0 += 64) {
        __syncthreads();
        const long long koff = ((long long)(b * TT + t0 + threadIdx.x)) * C3 + CC + h * DD;
        #pragma unroll
        for (int i = 0; i < DD; i += 4) {
            float4 k4 = *(const float4*)(qkv + koff + i);
            Ks[threadIdx.x][i] = k4.x; Ks[threadIdx.x][i + 1] = k4.y;
            Ks[threadIdx.x][i + 2] = k4.z; Ks[threadIdx.x][i + 3] = k4.w;
            float4 v4 = *(const float4*)(qkv + koff + CC + i);
            Vs[threadIdx.x][i] = v4.x; Vs[threadIdx.x][i + 1] = v4.y;
            Vs[threadIdx.x][i + 2] = v4.z; Vs[threadIdx.x][i + 3] = v4.w;
        }
        __syncthreads();

        const int jend = min(64, qi - t0 + 1);
        for (int j = 0; j < jend; j++) {
            float kx[DD];
            #pragma unroll
            for (int i = 0; i < DD; i += 4) {
                float4 t4 = *(const float4*)&Ks[j][i];
                kx[i] = t4.x; kx[i + 1] = t4.y; kx[i + 2] = t4.z; kx[i + 3] = t4.w;
            }
            float s0 = 0.f, s1 = 0.f, s2 = 0.f, s3 = 0.f;
            #pragma unroll
            for (int d = 0; d < DD; d += 4) {
                s0 = fmaf(qr[d],     kx[d],     s0);
                s1 = fmaf(qr[d + 1], kx[d + 1], s1);
                s2 = fmaf(qr[d + 2], kx[d + 2], s2);
                s3 = fmaf(qr[d + 3], kx[d + 3], s3);
            }
            float s = ((s0 + s1) + (s2 + s3)) * scale;
            float nm = fmaxf(m, s);
            float es = __expf(s - nm);
            float sc = __expf(m - nm);
            l = l * sc + es;
            #pragma unroll
            for (int d = 0; d < DD; d += 4) {
                float4 t4 = *(const float4*)&Vs[j][d];
                acc[d]     = fmaf(es, t4.x, acc[d]     * sc);
                acc[d + 1] = fmaf(es, t4.y, acc[d + 1] * sc);
                acc[d + 2] = fmaf(es, t4.z, acc[d + 2] * sc);
                acc[d + 3] = fmaf(es, t4.w, acc[d + 3] * sc);
            }
            m = nm;
        }
    }

    const float inv = 1.f / l;
    const long long aoff = ((long long)(b * TT + qi)) * CC + h * DD;
    #pragma unroll
    for (int d = 0; d < DD; d++) ao[aoff + d] = acc[d] * inv;
}

// ---------------- gating + inline compaction --------------------------------
__global__ void gate_k(const float* __restrict__ raw, const float* __restrict__ xnorm,
                       const float* __restrict__ snorm, const float* __restrict__ gates,
                       float* __restrict__ out_pre, float* __restrict__ out_am,
                       float* __restrict__ rw)
{
    const int token = blockIdx.x * 8 + threadIdx.y;
    const int e = threadIdx.x;

    float xn = fmaxf(xnorm[token], 1e-12f);
    float logit = raw[token * EE + e] / (xn * snorm[e]);
    float sig = 1.f / (1.f + __expf(-gates[e]));
    float pre = logit - sig;
    float gated = fmaxf(pre, 0.f);

    unsigned ballot = __ballot_sync(0xffffffffu, gated > 0.f);
    float am;
    if (ballot == 0u) {
        int rank = 0;
        #pragma unroll
        for (int j = 0; j < EE; j++) {
            float lj = __shfl_sync(0xffffffffu, logit, j);
            rank += (lj > logit) || (lj == logit && j < e);
        }
        am = (rank < (EE / 2)) ? 1.f : 0.f;
    } else {
        am = (gated > 0.f) ? 1.f : 0.f;
    }

    // inline compaction (list order irrelevant: GEMM rows independent)
    if (am > 0.f) {
        int i = atomicAdd(&g_cnt[e], 1);
        g_list[e * NN + i] = token;
    }

    float gl = (am > 0.f) ? gated : NEGF;
    float mx = gl;
    #pragma unroll
    for (int o = 16; o > 0; o >>= 1) mx = fmaxf(mx, __shfl_xor_sync(0xffffffffu, mx, o));
    float ev = __expf(gl - mx);
    float sm = ev;
    #pragma unroll
    for (int o = 16; o > 0; o >>= 1) sm += __shfl_xor_sync(0xffffffffu, sm, o);

    out_pre[token * EE + e] = pre;
    out_am [token * EE + e] = am;
    rw     [token * EE + e] = ev / sm;
}

// ---------------- zero expert counters ----------------
__global__ void zero_cnt_k()
{
    if (threadIdx.x < EE) g_cnt[threadIdx.x] = 0;
}

// ---------------- zero ONLY inactive (t,e) rows of feo ----------------------
__global__ void zero_inactive_k(const float* __restrict__ am, float4* __restrict__ feo)
{
    const int idx = blockIdx.x;                 // t*EE + e
    if (am[idx] > 0.f) return;
    feo[(long long)idx * (CC / 4) + threadIdx.x] = make_float4(0.f, 0.f, 0.f, 0.f);
}

// ---------------- moe combine + residual (skip exactly-zero weights) --------
__global__ void moe_reduce_k(const float* __restrict__ feo, const float* __restrict__ rw,
                             const float* __restrict__ hs, float* __restrict__ hsf)
{
    const int t = blockIdx.x, c = threadIdx.x;
    __shared__ float w[EE];
    if (c < EE) w[c] = rw[t * EE + c];
    __syncthreads();
    const float* f = feo + (long long)t * EE * CC + c;
    float s = 0.f;
    for (int e = 0; e < EE; e++) {
        float we = w[e];
        if (we != 0.f) s = fmaf(we, f[(long long)e * CC], s);
    }
    hsf[t * CC + c] = hs[t * CC + c] + s;
}

// ---------------- host-side launch helper ----------------
static void sgemm_al(const float* A, const float* B, float* C, const float* Src,
                     int M, int Nn, int K, int lda, int ldb, int ldc, int flags)
{
    dim3 grid((Nn + 127) / 128, (M + 127) / 128, 1);
    if (flags == 2)
        sgemm_k<2, true><<<grid, 256>>>(A, B, C, Src, M, Nn, K, lda, ldb, ldc);
    else
        sgemm_k<0, true><<<grid, 256>>>(A, B, C, Src, M, Nn, K, lda, ldb, ldc);
}

extern "C" void kernel_launch(void* const* d_in, const int* in_sizes, int n_in,
                              void* d_out, int out_size)
{
    const int*   ids   = (const int*)  d_in[0];
    const float* emb   = (const float*)d_in[1];
    const float* wq    = (const float*)d_in[2];
    const float* wk    = (const float*)d_in[3];
    const float* wv    = (const float*)d_in[4];
    const float* wo    = (const float*)d_in[5];
    const float* ln1w  = (const float*)d_in[6];
    const float* ln1b  = (const float*)d_in[7];
    const float* ln2w  = (const float*)d_in[8];
    const float* ln2b  = (const float*)d_in[9];
    const float* sim   = (const float*)d_in[10];
    const float* gates = (const float*)d_in[11];
    const float* w1    = (const float*)d_in[12];
    const float* w2    = (const float*)d_in[13];
    const float* lmh   = (const float*)d_in[14];

    float* out        = (float*)d_out;
    float* out_logits = out;                                       // [B,T,V]
    float* out_feo    = out_logits + (long long)BB * TT * VV;      // [N,E,C]
    float* out_pre    = out_feo    + (long long)NN * EE * CC;      // [N,E]
    float* out_am     = out_pre    + (long long)NN * EE;           // [N,E]

    float *hs, *x, *qkv, *wqkv, *ao, *xt, *hsf, *lraw, *rw, *xn, *sn, *hbuf;
    cudaGetSymbolAddress((void**)&hs,   g_hs);
    cudaGetSymbolAddress((void**)&x,    g_x);
    cudaGetSymbolAddress((void**)&qkv,  g_qkv);
    cudaGetSymbolAddress((void**)&wqkv, g_wqkv);
    cudaGetSymbolAddress((void**)&ao,   g_ao);
    cudaGetSymbolAddress((void**)&xt,   g_xt);
    cudaGetSymbolAddress((void**)&hsf,  g_hsf);
    cudaGetSymbolAddress((void**)&lraw, g_lraw);
    cudaGetSymbolAddress((void**)&rw,   g_rw);
    cudaGetSymbolAddress((void**)&xn,   g_xnorm);
    cudaGetSymbolAddress((void**)&sn,   g_snorm);
    cudaGetSymbolAddress((void**)&hbuf, g_h);

    // 1. fused embed + ln1; pack qkv weights; clear expert counters
    embed_ln1_k<<<NN, CC>>>(ids, emb, ln1w, ln1b, hs, x);
    pack_wqkv_k<<<CC, CC>>>(wq, wk, wv, wqkv);
    zero_cnt_k<<<1, 32>>>();
    // 2. fused q|k|v projection (fp32, 96 blocks)
    sgemm_al(x, wqkv, qkv, nullptr, NN, C3, CC, CC, C3, C3, 0);
    // 3. causal attention on packed layout
    attn_k<<<dim3(TT / 64, BB * HH), 64>>>(qkv, ao);
    // 4. hs += ao @ wo (fp32)
    sgemm_al(ao, wo, hs, hs, NN, CC, CC, CC, CC, CC, 2);
    // 5. ln2 (+ row norms for cosine gate)
    ln_k<<<NN, CC>>>(hs, ln2w, ln2b, xt, xn);
    // 6. sim column norms + raw gate logits (fp32 — mask-critical)
    snorm_k<<<EE, CC>>>(sim, sn);
    sgemm_al(xt, sim, lraw, nullptr, NN, EE, CC, CC, EE, EE, 0);
    // 7. gate + inline compaction
    gate_k<<<NN / 8, dim3(32, 8)>>>(lraw, xn, sn, gates, out_pre, out_am, rw);
    // 8. zero only inactive feo rows
    zero_inactive_k<<<NN * EE, 64>>>(out_am, (float4*)out_feo);
    // 9. expert up-proj + gelu (3xBF16 pre-split tensor cores)
    moe_up_bf16_k<<<dim3(FF / 128, NN / 128, EE), 256>>>(xt, w1, hbuf);
    // 10. expert down-proj, token-scatter (3xBF16 pre-split tensor cores)
    moe_down_bf16_k<<<dim3(CC / 128, NN / 128, EE), 256>>>(hbuf, w2, out_feo);
    // 11. moe combine + residual
    moe_reduce_k<<<NN, CC>>>(out_feo, rw, hs, hsf);
    // 12. lm head (3xBF16 pre-split; grid x=M for B-tile L2 reuse)
    lmhead_bf16_k<<<dim3(NN / 128, (VV + 127) / 128), 256>>>(hsf, lmh, out_logits,
                                                             NN, VV, CC, VV);
}